// round 1
// baseline (speedup 1.0000x reference)
#include <cuda_runtime.h>
#include <math.h>
#include <stdint.h>

#define N_TOKENS 8192
#define D_IN     1024
#define D_OUT    1024
#define N_EXP    8

#define BM 128
#define BN 128
#define BK 32
#define A_STRIDE 36    // 32 + 4 pad: conflict-free A fragment LDS
#define B_STRIDE 136   // 128 + 8 pad: conflict-free B fragment LDS

// gate probabilities scratch (device global: no allocation allowed in kernel_launch)
__device__ float g_gate[N_TOKENS * N_EXP];

// ---------------------------------------------------------------------------
// Gate: g = softmax(x @ gate_W + gate_b), one warp per token
// ---------------------------------------------------------------------------
__global__ void gate_kernel(const float* __restrict__ x,
                            const float* __restrict__ gate_W,
                            const float* __restrict__ gate_b) {
    int warp  = threadIdx.x >> 5;
    int lane  = threadIdx.x & 31;
    int token = blockIdx.x * 8 + warp;
    if (token >= N_TOKENS) return;

    const float* xr = x + (size_t)token * D_IN;
    float acc[N_EXP];
#pragma unroll
    for (int e = 0; e < N_EXP; e++) acc[e] = 0.f;

    for (int i = lane; i < D_IN; i += 32) {
        float xv = xr[i];
        const float4* gw = reinterpret_cast<const float4*>(gate_W + (size_t)i * N_EXP);
        float4 w0 = gw[0], w1 = gw[1];
        acc[0] += xv * w0.x; acc[1] += xv * w0.y;
        acc[2] += xv * w0.z; acc[3] += xv * w0.w;
        acc[4] += xv * w1.x; acc[5] += xv * w1.y;
        acc[6] += xv * w1.z; acc[7] += xv * w1.w;
    }
#pragma unroll
    for (int e = 0; e < N_EXP; e++) {
#pragma unroll
        for (int o = 16; o > 0; o >>= 1)
            acc[e] += __shfl_xor_sync(0xffffffffu, acc[e], o);
    }
    if (lane == 0) {
        float m = -1e30f;
#pragma unroll
        for (int e = 0; e < N_EXP; e++) { acc[e] += gate_b[e]; m = fmaxf(m, acc[e]); }
        float s = 0.f;
#pragma unroll
        for (int e = 0; e < N_EXP; e++) { acc[e] = expf(acc[e] - m); s += acc[e]; }
        float inv = 1.f / s;
#pragma unroll
        for (int e = 0; e < N_EXP; e++) g_gate[token * N_EXP + e] = acc[e] * inv;
    }
}

// ---------------------------------------------------------------------------
// TF32 helpers
// ---------------------------------------------------------------------------
__device__ __forceinline__ uint32_t f2tf32(float f) {
    uint32_t r;
    asm("cvt.rna.tf32.f32 %0, %1;" : "=r"(r) : "f"(f));
    return r;
}

__device__ __forceinline__ void mma_tf32(float* d, const uint32_t* a,
                                         const uint32_t* b, const float* c) {
    asm volatile(
        "mma.sync.aligned.m16n8k8.row.col.f32.tf32.tf32.f32 "
        "{%0,%1,%2,%3}, {%4,%5,%6,%7}, {%8,%9}, {%10,%11,%12,%13};\n"
        : "=f"(d[0]), "=f"(d[1]), "=f"(d[2]), "=f"(d[3])
        : "r"(a[0]), "r"(a[1]), "r"(a[2]), "r"(a[3]),
          "r"(b[0]), "r"(b[1]),
          "f"(c[0]), "f"(c[1]), "f"(c[2]), "f"(c[3]));
}

// ---------------------------------------------------------------------------
// Fused MoE GEMM: out = (g .* x broadcast over experts) @ W + (g @ b)
// Virtual GEMM: M=8192, N=1024, K=8*1024. A[n, e*1024+i] = g[n,e]*x[n,i].
// ---------------------------------------------------------------------------
__global__ void __launch_bounds__(256)
moe_gemm_kernel(const float* __restrict__ x,
                const float* __restrict__ W,
                const float* __restrict__ b,
                float* __restrict__ out) {
    __shared__ uint32_t A_s[BM * A_STRIDE];   // 128 x 32 tf32, padded
    __shared__ uint32_t B_s[BK * B_STRIDE];   // 32 x 128 tf32, padded
    __shared__ float    g_s[BM * N_EXP];      // gate tile
    __shared__ float    b_s[N_EXP * BN];      // bias tile

    const int tid = threadIdx.x;
    const int m0  = blockIdx.y * BM;
    const int n0  = blockIdx.x * BN;

    // load gate + bias tiles
    for (int i = tid; i < BM * N_EXP; i += 256)
        g_s[i] = g_gate[m0 * N_EXP + i];
    for (int i = tid; i < N_EXP * BN; i += 256) {
        int e = i / BN, c = i % BN;
        b_s[i] = b[(size_t)e * D_OUT + n0 + c];
    }
    __syncthreads();

    const int warp = tid >> 5, lane = tid & 31;
    const int wm = warp >> 2, wn = warp & 3;          // 2 x 4 warp grid
    const int gid = lane >> 2, tig = lane & 3;

    float acc[4][4][4];
#pragma unroll
    for (int mt = 0; mt < 4; mt++)
#pragma unroll
        for (int nt = 0; nt < 4; nt++)
#pragma unroll
            for (int j = 0; j < 4; j++) acc[mt][nt][j] = 0.f;

    // per-thread copy coordinates (fixed across iterations)
    int arow[4], ac4[4], bk_[4], bc4[4];
#pragma unroll
    for (int r = 0; r < 4; r++) {
        int idx = tid + r * 256;        // 0..1023
        arow[r] = idx >> 3;  ac4[r] = idx & 7;    // A: 128 rows x 8 float4
        bk_[r]  = idx >> 5;  bc4[r] = idx & 31;   // B: 32 rows  x 32 float4
    }

    const int ITERS = (N_EXP * D_IN) / BK;   // 256

    float4 pa[4], pb[4];

    // ---- prologue: load + store tile 0 ----
    {
        const int e = 0, kc = 0;
#pragma unroll
        for (int r = 0; r < 4; r++) {
            pa[r] = *reinterpret_cast<const float4*>(
                &x[(size_t)(m0 + arow[r]) * D_IN + kc + ac4[r] * 4]);
            pb[r] = *reinterpret_cast<const float4*>(
                &W[((size_t)e * D_IN + kc + bk_[r]) * D_OUT + n0 + bc4[r] * 4]);
        }
#pragma unroll
        for (int r = 0; r < 4; r++) {
            float gv = g_s[arow[r] * N_EXP + e];
            uint4 av;
            av.x = f2tf32(pa[r].x * gv); av.y = f2tf32(pa[r].y * gv);
            av.z = f2tf32(pa[r].z * gv); av.w = f2tf32(pa[r].w * gv);
            *reinterpret_cast<uint4*>(&A_s[arow[r] * A_STRIDE + ac4[r] * 4]) = av;
            uint4 bv;
            bv.x = f2tf32(pb[r].x); bv.y = f2tf32(pb[r].y);
            bv.z = f2tf32(pb[r].z); bv.w = f2tf32(pb[r].w);
            *reinterpret_cast<uint4*>(&B_s[bk_[r] * B_STRIDE + bc4[r] * 4]) = bv;
        }
    }
    __syncthreads();

    for (int it = 0; it < ITERS; ++it) {
        // ---- prefetch next tile into registers ----
        const int itn = it + 1;
        if (itn < ITERS) {
            const int e  = itn >> 5;
            const int kc = (itn & 31) * BK;
#pragma unroll
            for (int r = 0; r < 4; r++) {
                pa[r] = *reinterpret_cast<const float4*>(
                    &x[(size_t)(m0 + arow[r]) * D_IN + kc + ac4[r] * 4]);
                pb[r] = *reinterpret_cast<const float4*>(
                    &W[((size_t)e * D_IN + kc + bk_[r]) * D_OUT + n0 + bc4[r] * 4]);
            }
        }

        // ---- compute on current tile ----
#pragma unroll
        for (int ks = 0; ks < 4; ks++) {
            const int k0 = ks * 8;
            uint32_t af[4][4];
#pragma unroll
            for (int mt = 0; mt < 4; mt++) {
                int r = wm * 64 + mt * 16 + gid;
                af[mt][0] = A_s[r * A_STRIDE + k0 + tig];
                af[mt][1] = A_s[(r + 8) * A_STRIDE + k0 + tig];
                af[mt][2] = A_s[r * A_STRIDE + k0 + tig + 4];
                af[mt][3] = A_s[(r + 8) * A_STRIDE + k0 + tig + 4];
            }
            uint32_t bf[4][2];
#pragma unroll
            for (int nt = 0; nt < 4; nt++) {
                int c = wn * 32 + nt * 8 + gid;
                bf[nt][0] = B_s[(k0 + tig) * B_STRIDE + c];
                bf[nt][1] = B_s[(k0 + tig + 4) * B_STRIDE + c];
            }
#pragma unroll
            for (int mt = 0; mt < 4; mt++)
#pragma unroll
                for (int nt = 0; nt < 4; nt++)
                    mma_tf32(acc[mt][nt], af[mt], bf[nt], acc[mt][nt]);
        }
        __syncthreads();

        // ---- store prefetched tile to smem ----
        if (itn < ITERS) {
            const int e = itn >> 5;
#pragma unroll
            for (int r = 0; r < 4; r++) {
                float gv = g_s[arow[r] * N_EXP + e];
                uint4 av;
                av.x = f2tf32(pa[r].x * gv); av.y = f2tf32(pa[r].y * gv);
                av.z = f2tf32(pa[r].z * gv); av.w = f2tf32(pa[r].w * gv);
                *reinterpret_cast<uint4*>(&A_s[arow[r] * A_STRIDE + ac4[r] * 4]) = av;
                uint4 bv;
                bv.x = f2tf32(pb[r].x); bv.y = f2tf32(pb[r].y);
                bv.z = f2tf32(pb[r].z); bv.w = f2tf32(pb[r].w);
                *reinterpret_cast<uint4*>(&B_s[bk_[r] * B_STRIDE + bc4[r] * 4]) = bv;
            }
            __syncthreads();
        }
    }

    // ---- epilogue: add gated bias, store ----
#pragma unroll
    for (int mt = 0; mt < 4; mt++) {
        int r = wm * 64 + mt * 16 + gid;
#pragma unroll
        for (int nt = 0; nt < 4; nt++) {
            int c = wn * 32 + nt * 8 + 2 * tig;
#pragma unroll
            for (int half = 0; half < 2; half++) {
                int rr = r + half * 8;
                float bias0 = 0.f, bias1 = 0.f;
#pragma unroll
                for (int e = 0; e < N_EXP; e++) {
                    float gv = g_s[rr * N_EXP + e];
                    bias0 += gv * b_s[e * BN + c];
                    bias1 += gv * b_s[e * BN + c + 1];
                }
                float2 v;
                v.x = acc[mt][nt][half * 2 + 0] + bias0;
                v.y = acc[mt][nt][half * 2 + 1] + bias1;
                *reinterpret_cast<float2*>(&out[(size_t)(m0 + rr) * D_OUT + n0 + c]) = v;
            }
        }
    }
}

// ---------------------------------------------------------------------------
extern "C" void kernel_launch(void* const* d_in, const int* in_sizes, int n_in,
                              void* d_out, int out_size) {
    const float* x      = (const float*)d_in[0];
    const float* W      = (const float*)d_in[1];
    const float* b      = (const float*)d_in[2];
    const float* gate_W = (const float*)d_in[3];
    const float* gate_b = (const float*)d_in[4];
    float* out = (float*)d_out;

    gate_kernel<<<N_TOKENS / 8, 256>>>(x, gate_W, gate_b);

    dim3 grid(D_OUT / BN, N_TOKENS / BM);   // (8, 64) = 512 CTAs
    moe_gemm_kernel<<<grid, 256>>>(x, W, b, out);
}

// round 3
// speedup vs baseline: 1.7422x; 1.7422x over previous
#include <cuda_runtime.h>
#include <math.h>
#include <stdint.h>

#define N_TOKENS 8192
#define D_IN     1024
#define D_OUT    1024
#define N_EXP    8

#define BM 256
#define BN 128
#define BK 32
#define KCH 32                   // k-chunks per expert
#define MT  (N_TOKENS / BM)      // 32
#define NT  (D_OUT / BN)         // 8
#define ITERS (N_EXP * KCH)      // 256

#define A_TILE_BYTES 32768       // 256 x 32 tf32, fragment-packed
#define B_TILE_BYTES 16384       // 32 x 128 tf32, fragment-packed
#define STAGE_BYTES  (A_TILE_BYTES + B_TILE_BYTES)   // 49152
#define SMEM_G   (2 * STAGE_BYTES)    // 98304 : gate tile 256x8
#define SMEM_BS  (SMEM_G + 8192)      // 106496: bias tile 8x128
#define SMEM_TOTAL (SMEM_BS + 4096)   // 110592

// ---------------------------------------------------------------------------
// scratch (device globals: no allocation allowed)
// ---------------------------------------------------------------------------
__device__ float g_gate[N_TOKENS * N_EXP];
__device__ float a_pack[(size_t)N_EXP * MT * KCH * 8192];   // 256 MB
__device__ float w_pack[(size_t)N_EXP * NT * KCH * 4096];   // 32 MB

// ---------------------------------------------------------------------------
// helpers
// ---------------------------------------------------------------------------
__device__ __forceinline__ uint32_t smem_u32(const void* p) {
    uint32_t a;
    asm("{ .reg .u64 t; cvta.to.shared.u64 t, %1; cvt.u32.u64 %0, t; }" : "=r"(a) : "l"(p));
    return a;
}
__device__ __forceinline__ void cp16(uint32_t d, const void* s) {
    asm volatile("cp.async.cg.shared.global [%0], [%1], 16;" :: "r"(d), "l"(s));
}
__device__ __forceinline__ void cp_commit() {
    asm volatile("cp.async.commit_group;" ::: "memory");
}
__device__ __forceinline__ void cp_wait1() {
    asm volatile("cp.async.wait_group 1;" ::: "memory");
}
__device__ __forceinline__ void cp_wait0() {
    asm volatile("cp.async.wait_group 0;" ::: "memory");
}
__device__ __forceinline__ float tf32r(float f) {
    uint32_t r;
    asm("cvt.rna.tf32.f32 %0, %1;" : "=r"(r) : "f"(f));
    return __uint_as_float(r);
}
__device__ __forceinline__ void mma_tf32(float* d, const uint32_t* a,
                                         const uint32_t* b, const float* c) {
    asm volatile(
        "mma.sync.aligned.m16n8k8.row.col.f32.tf32.tf32.f32 "
        "{%0,%1,%2,%3}, {%4,%5,%6,%7}, {%8,%9}, {%10,%11,%12,%13};\n"
        : "=f"(d[0]), "=f"(d[1]), "=f"(d[2]), "=f"(d[3])
        : "r"(a[0]), "r"(a[1]), "r"(a[2]), "r"(a[3]),
          "r"(b[0]), "r"(b[1]),
          "f"(c[0]), "f"(c[1]), "f"(c[2]), "f"(c[3]));
}

// ---------------------------------------------------------------------------
// Gate: g = softmax(x @ gate_W + gate_b), one warp per token
// ---------------------------------------------------------------------------
__global__ void gate_kernel(const float* __restrict__ x,
                            const float* __restrict__ gate_W,
                            const float* __restrict__ gate_b) {
    int warp = threadIdx.x >> 5, lane = threadIdx.x & 31;
    int token = blockIdx.x * 8 + warp;
    if (token >= N_TOKENS) return;
    const float* xr = x + (size_t)token * D_IN;
    float acc[N_EXP];
#pragma unroll
    for (int e = 0; e < N_EXP; e++) acc[e] = 0.f;
    for (int i = lane; i < D_IN; i += 32) {
        float xv = xr[i];
        const float4* gw = reinterpret_cast<const float4*>(gate_W + (size_t)i * N_EXP);
        float4 w0 = gw[0], w1 = gw[1];
        acc[0] += xv * w0.x; acc[1] += xv * w0.y; acc[2] += xv * w0.z; acc[3] += xv * w0.w;
        acc[4] += xv * w1.x; acc[5] += xv * w1.y; acc[6] += xv * w1.z; acc[7] += xv * w1.w;
    }
#pragma unroll
    for (int e = 0; e < N_EXP; e++)
#pragma unroll
        for (int o = 16; o > 0; o >>= 1)
            acc[e] += __shfl_xor_sync(0xffffffffu, acc[e], o);
    if (lane == 0) {
        float m = -1e30f;
#pragma unroll
        for (int e = 0; e < N_EXP; e++) { acc[e] += gate_b[e]; m = fmaxf(m, acc[e]); }
        float s = 0.f;
#pragma unroll
        for (int e = 0; e < N_EXP; e++) { acc[e] = expf(acc[e] - m); s += acc[e]; }
        float inv = 1.f / s;
#pragma unroll
        for (int e = 0; e < N_EXP; e++) g_gate[token * N_EXP + e] = acc[e] * inv;
    }
}

// ---------------------------------------------------------------------------
// pack_a: a_pack[e][mt][kc] = 256x32 tile of g[n,e]*x[n,i], tf32, fragment layout.
// Entry (ks 0..3, m16 0..15, lane 0..31) = 4 words {a0,a1,a2,a3} for mma m16n8k8.
// ---------------------------------------------------------------------------
__global__ void pack_a_kernel(const float* __restrict__ x) {
    __shared__ float xs[256 * 36];   // stride 36: float4-aligned + conflict-free gather
    __shared__ float gs[256];
    const int blk = blockIdx.x;                  // e*1024 + mtb*32 + kc
    const int kc = blk & 31, mtb = (blk >> 5) & 31, e = blk >> 10;
    const int tid = threadIdx.x;

    const float* src = x + (size_t)(mtb * 256) * D_IN + kc * 32;
    for (int idx = tid; idx < 2048; idx += 256) {
        int row = idx >> 3, c4 = idx & 7;
        float4 v = *reinterpret_cast<const float4*>(src + (size_t)row * D_IN + c4 * 4);
        *reinterpret_cast<float4*>(xs + row * 36 + c4 * 4) = v;
    }
    if (tid < 256) gs[tid] = g_gate[(size_t)(mtb * 256 + tid) * N_EXP + e];
    __syncthreads();

    float* dst = a_pack + (size_t)blk * 8192;
    for (int ent = tid; ent < 2048; ent += 256) {
        int lane = ent & 31, m16 = (ent >> 5) & 15, ks = ent >> 9;
        int gid = lane >> 2, tig = lane & 3;
        int r0 = m16 * 16 + gid, r1 = r0 + 8, c0 = ks * 8 + tig;
        float g0 = gs[r0], g1 = gs[r1];
        float4 w;
        w.x = tf32r(g0 * xs[r0 * 36 + c0]);
        w.y = tf32r(g1 * xs[r1 * 36 + c0]);
        w.z = tf32r(g0 * xs[r0 * 36 + c0 + 4]);
        w.w = tf32r(g1 * xs[r1 * 36 + c0 + 4]);
        *reinterpret_cast<float4*>(dst + ent * 4) = w;
    }
}

// ---------------------------------------------------------------------------
// pack_w: w_pack[e][nt][kc] = 32(k)x128(n) tile of W^T, tf32, fragment layout.
// Entry (ks 0..3, jpair 0..7, lane) = {b0(j0),b1(j0),b0(j1),b1(j1)}.
// ---------------------------------------------------------------------------
__global__ void pack_w_kernel(const float* __restrict__ W) {
    __shared__ float ws[32 * 132];
    const int blk = blockIdx.x;                  // e*256 + nt*32 + kc
    const int kc = blk & 31, nt = (blk >> 5) & 7, e = blk >> 8;
    const int tid = threadIdx.x;

    const float* src = W + ((size_t)e * D_IN + kc * 32) * D_OUT + nt * 128;
    for (int idx = tid; idx < 1024; idx += 256) {
        int il = idx >> 5, o4 = idx & 31;
        float4 v = *reinterpret_cast<const float4*>(src + (size_t)il * D_OUT + o4 * 4);
        *reinterpret_cast<float4*>(ws + il * 132 + o4 * 4) = v;
    }
    __syncthreads();

    float* dst = w_pack + (size_t)blk * 4096;
    for (int ent = tid; ent < 1024; ent += 256) {
        int lane = ent & 31, jp = (ent >> 5) & 7, ks = ent >> 8;
        int gid = lane >> 2, tig = lane & 3;
        int k0 = ks * 8 + tig, c0 = jp * 16 + gid;
        float4 w;
        w.x = tf32r(ws[k0 * 132 + c0]);
        w.y = tf32r(ws[(k0 + 4) * 132 + c0]);
        w.z = tf32r(ws[k0 * 132 + c0 + 8]);
        w.w = tf32r(ws[(k0 + 4) * 132 + c0 + 8]);
        *reinterpret_cast<float4*>(dst + ent * 4) = w;
    }
}

// ---------------------------------------------------------------------------
// Hot GEMM: 256x128 tile per CTA, 8 warps as 4(m) x 2(n), warp tile 64x64.
// All operand bytes flow: cp.async 16B -> SMEM -> LDS.128 fragment -> MMA.
// ---------------------------------------------------------------------------
__global__ void __launch_bounds__(256, 1)
moe_mma_kernel(const float* __restrict__ bias, float* __restrict__ out) {
    extern __shared__ char smem[];
    const int tid = threadIdx.x, wid = tid >> 5, lane = tid & 31;
    const int gid = lane >> 2, tig = lane & 3;
    const int wm = wid >> 1, wn = wid & 1;
    const int nt = blockIdx.x & 7, mt = blockIdx.x >> 3;
    const int m0 = mt * BM, n0 = nt * BN;
    const uint32_t sb = smem_u32(smem);

    float* g_s = reinterpret_cast<float*>(smem + SMEM_G);
    float* b_s = reinterpret_cast<float*>(smem + SMEM_BS);
    for (int i = tid; i < BM * N_EXP; i += 256) g_s[i] = g_gate[m0 * N_EXP + i];
    for (int i = tid; i < N_EXP * BN; i += 256)
        b_s[i] = bias[(size_t)(i >> 7) * D_OUT + n0 + (i & 127)];

    float acc[4][8][4];
#pragma unroll
    for (int a = 0; a < 4; a++)
#pragma unroll
        for (int b = 0; b < 8; b++)
#pragma unroll
            for (int c = 0; c < 4; c++) acc[a][b][c] = 0.f;

    // ---- prologue: stage 0 ----
    {
        const char* asrc = (const char*)(a_pack + (size_t)(mt * KCH) * 8192);     // e=0,kc=0
        const char* bsrc = (const char*)(w_pack + (size_t)(nt * KCH) * 4096);
        uint32_t d = sb + tid * 16;
#pragma unroll
        for (int r = 0; r < 8; r++) cp16(d + r * 4096, asrc + tid * 16 + r * 4096);
#pragma unroll
        for (int r = 0; r < 4; r++) cp16(d + A_TILE_BYTES + r * 4096, bsrc + tid * 16 + r * 4096);
        cp_commit();
    }

    for (int it = 0; it < ITERS; ++it) {
        const int s = it & 1;
        if (it + 1 < ITERS) {
            const int e = (it + 1) >> 5, kc = (it + 1) & 31;
            const char* asrc = (const char*)(a_pack + (size_t)((e * MT + mt) * KCH + kc) * 8192);
            const char* bsrc = (const char*)(w_pack + (size_t)((e * NT + nt) * KCH + kc) * 4096);
            uint32_t d = sb + (s ^ 1) * STAGE_BYTES + tid * 16;
#pragma unroll
            for (int r = 0; r < 8; r++) cp16(d + r * 4096, asrc + tid * 16 + r * 4096);
#pragma unroll
            for (int r = 0; r < 4; r++) cp16(d + A_TILE_BYTES + r * 4096, bsrc + tid * 16 + r * 4096);
            cp_commit();
            cp_wait1();
        } else {
            cp_wait0();
        }
        __syncthreads();

        const char* ab = smem + s * STAGE_BYTES;
        const char* bb = ab + A_TILE_BYTES;
#pragma unroll
        for (int ks = 0; ks < 4; ks++) {
            uint4 af[4], bf[4];
#pragma unroll
            for (int mtt = 0; mtt < 4; mtt++)
                af[mtt] = *reinterpret_cast<const uint4*>(
                    ab + (size_t)(((ks * 16) + (wm * 4 + mtt)) * 32 + lane) * 16);
#pragma unroll
            for (int jp = 0; jp < 4; jp++)
                bf[jp] = *reinterpret_cast<const uint4*>(
                    bb + (size_t)(((ks * 8) + (wn * 4 + jp)) * 32 + lane) * 16);
#pragma unroll
            for (int mtt = 0; mtt < 4; mtt++)
#pragma unroll
                for (int ntt = 0; ntt < 8; ntt++) {
                    const uint32_t* a = reinterpret_cast<const uint32_t*>(&af[mtt]);
                    const uint32_t* bp =
                        reinterpret_cast<const uint32_t*>(&bf[ntt >> 1]) + (ntt & 1) * 2;
                    mma_tf32(acc[mtt][ntt], a, bp, acc[mtt][ntt]);
                }
        }
        __syncthreads();
    }

    // ---- epilogue: gated bias + store ----
#pragma unroll
    for (int mtt = 0; mtt < 4; mtt++) {
        const int rb = wm * 64 + mtt * 16 + gid;
#pragma unroll
        for (int half = 0; half < 2; half++) {
            const int r = rb + half * 8;
            const float* gr = g_s + r * N_EXP;
            float* orow = out + (size_t)(m0 + r) * D_OUT + n0;
#pragma unroll
            for (int ntt = 0; ntt < 8; ntt++) {
                const int c = wn * 64 + ntt * 8 + 2 * tig;
                float b0 = 0.f, b1 = 0.f;
#pragma unroll
                for (int e = 0; e < N_EXP; e++) {
                    float gv = gr[e];
                    b0 += gv * b_s[e * BN + c];
                    b1 += gv * b_s[e * BN + c + 1];
                }
                float2 v;
                v.x = acc[mtt][ntt][half * 2 + 0] + b0;
                v.y = acc[mtt][ntt][half * 2 + 1] + b1;
                *reinterpret_cast<float2*>(orow + c) = v;
            }
        }
    }
}

// ---------------------------------------------------------------------------
extern "C" void kernel_launch(void* const* d_in, const int* in_sizes, int n_in,
                              void* d_out, int out_size) {
    const float* x      = (const float*)d_in[0];
    const float* W      = (const float*)d_in[1];
    const float* b      = (const float*)d_in[2];
    const float* gate_W = (const float*)d_in[3];
    const float* gate_b = (const float*)d_in[4];
    float* out = (float*)d_out;

    gate_kernel<<<N_TOKENS / 8, 256>>>(x, gate_W, gate_b);
    pack_a_kernel<<<N_EXP * MT * KCH, 256>>>(x);   // 8192 blocks
    pack_w_kernel<<<N_EXP * NT * KCH, 256>>>(W);   // 2048 blocks

    static int smem_set = 0;
    if (!smem_set) {
        cudaFuncSetAttribute(moe_mma_kernel,
                             cudaFuncAttributeMaxDynamicSharedMemorySize, SMEM_TOTAL);
        smem_set = 1;
    }
    moe_mma_kernel<<<MT * NT, 256, SMEM_TOTAL>>>(b, out);   // 256 CTAs
}

// round 4
// speedup vs baseline: 2.9288x; 1.6811x over previous
#include <cuda_runtime.h>
#include <cuda_fp16.h>
#include <math.h>
#include <stdint.h>

#define N_TOKENS 8192
#define D_IN     1024
#define D_OUT    1024
#define N_EXP    8

#define BM 256
#define BN 128
#define BK 32
#define KCH 32                   // k-chunks per expert
#define MT  (N_TOKENS / BM)      // 32
#define NT  (D_OUT / BN)         // 8
#define ITERS (N_EXP * KCH)      // 256
#define NSTAGE 3

#define A_TILE_BYTES 16384       // 256 x 32 fp16, fragment-packed
#define B_TILE_BYTES 8192        // 32 x 128 fp16, fragment-packed
#define STAGE_BYTES  (A_TILE_BYTES + B_TILE_BYTES)     // 24576
#define SMEM_G   (NSTAGE * STAGE_BYTES)                // 73728 : gate 256x8 f32
#define SMEM_BS  (SMEM_G + 8192)                       // 81920 : bias 8x128 f32
#define SMEM_TOTAL (SMEM_BS + 4096)                    // 86016

// ---------------------------------------------------------------------------
// scratch (device globals: no allocation allowed)
// ---------------------------------------------------------------------------
__device__ float  g_gate[N_TOKENS * N_EXP];
__device__ __half a_pack[(size_t)N_EXP * MT * KCH * 8192];   // 128 MB
__device__ __half w_pack[(size_t)N_EXP * NT * KCH * 4096];   // 16 MB

// ---------------------------------------------------------------------------
// helpers
// ---------------------------------------------------------------------------
__device__ __forceinline__ uint32_t smem_u32(const void* p) {
    uint32_t a;
    asm("{ .reg .u64 t; cvta.to.shared.u64 t, %1; cvt.u32.u64 %0, t; }" : "=r"(a) : "l"(p));
    return a;
}
__device__ __forceinline__ void cp16(uint32_t d, const void* s) {
    asm volatile("cp.async.cg.shared.global [%0], [%1], 16;" :: "r"(d), "l"(s));
}
__device__ __forceinline__ void cp_commit() {
    asm volatile("cp.async.commit_group;" ::: "memory");
}
__device__ __forceinline__ void cp_wait1() {
    asm volatile("cp.async.wait_group 1;" ::: "memory");
}
__device__ __forceinline__ void mma_f16(float* d, const uint32_t* a,
                                        const uint32_t* b, const float* c) {
    asm volatile(
        "mma.sync.aligned.m16n8k16.row.col.f32.f16.f16.f32 "
        "{%0,%1,%2,%3}, {%4,%5,%6,%7}, {%8,%9}, {%10,%11,%12,%13};\n"
        : "=f"(d[0]), "=f"(d[1]), "=f"(d[2]), "=f"(d[3])
        : "r"(a[0]), "r"(a[1]), "r"(a[2]), "r"(a[3]),
          "r"(b[0]), "r"(b[1]),
          "f"(c[0]), "f"(c[1]), "f"(c[2]), "f"(c[3]));
}
__device__ __forceinline__ uint32_t h2u(float lo, float hi) {
    __half2 h = __halves2half2(__float2half_rn(lo), __float2half_rn(hi));
    return *reinterpret_cast<uint32_t*>(&h);
}

// ---------------------------------------------------------------------------
// Gate: g = softmax(x @ gate_W + gate_b), one warp per token
// ---------------------------------------------------------------------------
__global__ void gate_kernel(const float* __restrict__ x,
                            const float* __restrict__ gate_W,
                            const float* __restrict__ gate_b) {
    int warp = threadIdx.x >> 5, lane = threadIdx.x & 31;
    int token = blockIdx.x * 8 + warp;
    if (token >= N_TOKENS) return;
    const float* xr = x + (size_t)token * D_IN;
    float acc[N_EXP];
#pragma unroll
    for (int e = 0; e < N_EXP; e++) acc[e] = 0.f;
    for (int i = lane; i < D_IN; i += 32) {
        float xv = xr[i];
        const float4* gw = reinterpret_cast<const float4*>(gate_W + (size_t)i * N_EXP);
        float4 w0 = gw[0], w1 = gw[1];
        acc[0] += xv * w0.x; acc[1] += xv * w0.y; acc[2] += xv * w0.z; acc[3] += xv * w0.w;
        acc[4] += xv * w1.x; acc[5] += xv * w1.y; acc[6] += xv * w1.z; acc[7] += xv * w1.w;
    }
#pragma unroll
    for (int e = 0; e < N_EXP; e++)
#pragma unroll
        for (int o = 16; o > 0; o >>= 1)
            acc[e] += __shfl_xor_sync(0xffffffffu, acc[e], o);
    if (lane == 0) {
        float m = -1e30f;
#pragma unroll
        for (int e = 0; e < N_EXP; e++) { acc[e] += gate_b[e]; m = fmaxf(m, acc[e]); }
        float s = 0.f;
#pragma unroll
        for (int e = 0; e < N_EXP; e++) { acc[e] = expf(acc[e] - m); s += acc[e]; }
        float inv = 1.f / s;
#pragma unroll
        for (int e = 0; e < N_EXP; e++) g_gate[token * N_EXP + e] = acc[e] * inv;
    }
}

// ---------------------------------------------------------------------------
// pack_a: a_pack[e][mt][kc] = 256x32 tile of g[n,e]*x[n,i], fp16, fragment layout
// for mma.m16n8k16: entry (ks2, m16, lane) = {a0,a1,a2,a3} packed half2s.
// ---------------------------------------------------------------------------
__global__ void pack_a_kernel(const float* __restrict__ x) {
    __shared__ float xs[256 * 36];
    __shared__ float gs[256];
    const int blk = blockIdx.x;                  // e*1024 + mtb*32 + kc
    const int kc = blk & 31, mtb = (blk >> 5) & 31, e = blk >> 10;
    const int tid = threadIdx.x;

    const float* src = x + (size_t)(mtb * 256) * D_IN + kc * 32;
    for (int idx = tid; idx < 2048; idx += 256) {
        int row = idx >> 3, c4 = idx & 7;
        float4 v = *reinterpret_cast<const float4*>(src + (size_t)row * D_IN + c4 * 4);
        *reinterpret_cast<float4*>(xs + row * 36 + c4 * 4) = v;
    }
    gs[tid] = g_gate[(size_t)(mtb * 256 + tid) * N_EXP + e];
    __syncthreads();

    __half* dst = a_pack + (size_t)blk * 8192;
#pragma unroll
    for (int q = 0; q < 4; q++) {
        int ent = tid + q * 256;                 // 0..1023
        int lane = ent & 31, m16 = (ent >> 5) & 15, ks2 = ent >> 9;
        int gid = lane >> 2, tig = lane & 3;
        int r0 = m16 * 16 + gid, r1 = r0 + 8, c0 = ks2 * 16 + 2 * tig;
        float g0 = gs[r0], g1 = gs[r1];
        const float* x0 = xs + r0 * 36;
        const float* x1 = xs + r1 * 36;
        uint4 w;
        w.x = h2u(g0 * x0[c0],     g0 * x0[c0 + 1]);
        w.y = h2u(g1 * x1[c0],     g1 * x1[c0 + 1]);
        w.z = h2u(g0 * x0[c0 + 8], g0 * x0[c0 + 9]);
        w.w = h2u(g1 * x1[c0 + 8], g1 * x1[c0 + 9]);
        *reinterpret_cast<uint4*>(dst + ent * 8) = w;
    }
}

// ---------------------------------------------------------------------------
// pack_w: w_pack[e][nt][kc] = 32(k)x128(n) tile of W^T, fp16, fragment layout.
// Entry (ks2, jp, lane) = {b0(j0),b1(j0),b0(j1),b1(j1)} packed half2s.
// ---------------------------------------------------------------------------
__global__ void pack_w_kernel(const float* __restrict__ W) {
    __shared__ float ws[32 * 132];
    const int blk = blockIdx.x;                  // e*256 + nt*32 + kc
    const int kc = blk & 31, nt = (blk >> 5) & 7, e = blk >> 8;
    const int tid = threadIdx.x;

    const float* src = W + ((size_t)e * D_IN + kc * 32) * D_OUT + nt * 128;
    for (int idx = tid; idx < 1024; idx += 256) {
        int il = idx >> 5, o4 = idx & 31;
        float4 v = *reinterpret_cast<const float4*>(src + (size_t)il * D_OUT + o4 * 4);
        *reinterpret_cast<float4*>(ws + il * 132 + o4 * 4) = v;
    }
    __syncthreads();

    __half* dst = w_pack + (size_t)blk * 4096;
#pragma unroll
    for (int q = 0; q < 2; q++) {
        int ent = tid + q * 256;                 // 0..511
        int lane = ent & 31, jp = (ent >> 5) & 7, ks2 = ent >> 8;
        int gid = lane >> 2, tig = lane & 3;
        int kr = ks2 * 16 + 2 * tig;
        int cA = jp * 16 + gid, cB = cA + 8;
        uint4 w;
        w.x = h2u(ws[kr * 132 + cA],       ws[(kr + 1) * 132 + cA]);
        w.y = h2u(ws[(kr + 8) * 132 + cA], ws[(kr + 9) * 132 + cA]);
        w.z = h2u(ws[kr * 132 + cB],       ws[(kr + 1) * 132 + cB]);
        w.w = h2u(ws[(kr + 8) * 132 + cB], ws[(kr + 9) * 132 + cB]);
        *reinterpret_cast<uint4*>(dst + ent * 8) = w;
    }
}

// ---------------------------------------------------------------------------
// Hot GEMM: 256x128 tile per CTA, 8 warps 4(m) x 2(n), warp tile 64x64.
// fp16 m16n8k16, 3-stage cp.async pipeline, one barrier per iteration.
// ---------------------------------------------------------------------------
__global__ void __launch_bounds__(256, 1)
moe_mma_kernel(const float* __restrict__ bias, float* __restrict__ out) {
    extern __shared__ char smem[];
    const int tid = threadIdx.x, wid = tid >> 5, lane = tid & 31;
    const int gid = lane >> 2, tig = lane & 3;
    const int wm = wid >> 1, wn = wid & 1;
    const int nt = blockIdx.x & 7, mt = blockIdx.x >> 3;
    const int m0 = mt * BM, n0 = nt * BN;
    const uint32_t sb = smem_u32(smem);

    float* g_s = reinterpret_cast<float*>(smem + SMEM_G);
    float* b_s = reinterpret_cast<float*>(smem + SMEM_BS);
    for (int i = tid; i < BM * N_EXP; i += 256) g_s[i] = g_gate[m0 * N_EXP + i];
    for (int i = tid; i < N_EXP * BN; i += 256)
        b_s[i] = bias[(size_t)(i >> 7) * D_OUT + n0 + (i & 127)];

    float acc[4][8][4];
#pragma unroll
    for (int a = 0; a < 4; a++)
#pragma unroll
        for (int b = 0; b < 8; b++)
#pragma unroll
            for (int c = 0; c < 4; c++) acc[a][b][c] = 0.f;

    // per-thread cp.async source/dest offsets: A = 4 x 16B, B = 2 x 16B
    // issue one stage
    auto issue = [&](int it, int buf) {
        const int e = it >> 5, kc = it & 31;
        const char* asrc = (const char*)(a_pack + (size_t)((e * MT + mt) * KCH + kc) * 8192);
        const char* bsrc = (const char*)(w_pack + (size_t)((e * NT + nt) * KCH + kc) * 4096);
        uint32_t d = sb + buf * STAGE_BYTES + tid * 16;
#pragma unroll
        for (int r = 0; r < 4; r++) cp16(d + r * 4096, asrc + tid * 16 + r * 4096);
#pragma unroll
        for (int r = 0; r < 2; r++) cp16(d + A_TILE_BYTES + r * 4096, bsrc + tid * 16 + r * 4096);
        cp_commit();
    };

    issue(0, 0);
    issue(1, 1);

    for (int it = 0; it < ITERS; ++it) {
        cp_wait1();                 // stage it landed (<=1 group still in flight)
        __syncthreads();            // publish to all threads; stage it-1 fully read
        if (it + 2 < ITERS) issue(it + 2, (it + 2) % NSTAGE);

        const char* ab = smem + (it % NSTAGE) * STAGE_BYTES;
        const char* bb = ab + A_TILE_BYTES;
#pragma unroll
        for (int ks2 = 0; ks2 < 2; ks2++) {
            uint4 af[4], bf[4];
#pragma unroll
            for (int mtt = 0; mtt < 4; mtt++)
                af[mtt] = *reinterpret_cast<const uint4*>(
                    ab + (size_t)((ks2 * 16 + wm * 4 + mtt) * 32 + lane) * 16);
#pragma unroll
            for (int jp = 0; jp < 4; jp++)
                bf[jp] = *reinterpret_cast<const uint4*>(
                    bb + (size_t)((ks2 * 8 + wn * 4 + jp) * 32 + lane) * 16);
#pragma unroll
            for (int mtt = 0; mtt < 4; mtt++)
#pragma unroll
                for (int ntt = 0; ntt < 8; ntt++) {
                    const uint32_t* a = reinterpret_cast<const uint32_t*>(&af[mtt]);
                    const uint32_t* bp =
                        reinterpret_cast<const uint32_t*>(&bf[ntt >> 1]) + (ntt & 1) * 2;
                    mma_f16(acc[mtt][ntt], a, bp, acc[mtt][ntt]);
                }
        }
    }

    // ---- epilogue: gated bias + store ----
#pragma unroll
    for (int mtt = 0; mtt < 4; mtt++) {
        const int rb = wm * 64 + mtt * 16 + gid;
#pragma unroll
        for (int half = 0; half < 2; half++) {
            const int r = rb + half * 8;
            const float* gr = g_s + r * N_EXP;
            float* orow = out + (size_t)(m0 + r) * D_OUT + n0;
#pragma unroll
            for (int ntt = 0; ntt < 8; ntt++) {
                const int c = wn * 64 + ntt * 8 + 2 * tig;
                float b0 = 0.f, b1 = 0.f;
#pragma unroll
                for (int e = 0; e < N_EXP; e++) {
                    float gv = gr[e];
                    b0 += gv * b_s[e * BN + c];
                    b1 += gv * b_s[e * BN + c + 1];
                }
                float2 v;
                v.x = acc[mtt][ntt][half * 2 + 0] + b0;
                v.y = acc[mtt][ntt][half * 2 + 1] + b1;
                *reinterpret_cast<float2*>(orow + c) = v;
            }
        }
    }
}

// ---------------------------------------------------------------------------
extern "C" void kernel_launch(void* const* d_in, const int* in_sizes, int n_in,
                              void* d_out, int out_size) {
    const float* x      = (const float*)d_in[0];
    const float* W      = (const float*)d_in[1];
    const float* b      = (const float*)d_in[2];
    const float* gate_W = (const float*)d_in[3];
    const float* gate_b = (const float*)d_in[4];
    float* out = (float*)d_out;

    gate_kernel<<<N_TOKENS / 8, 256>>>(x, gate_W, gate_b);
    pack_a_kernel<<<N_EXP * MT * KCH, 256>>>(x);   // 8192 blocks
    pack_w_kernel<<<N_EXP * NT * KCH, 256>>>(W);   // 2048 blocks

    static int smem_set = 0;
    if (!smem_set) {
        cudaFuncSetAttribute(moe_mma_kernel,
                             cudaFuncAttributeMaxDynamicSharedMemorySize, SMEM_TOTAL);
        smem_set = 1;
    }
    moe_mma_kernel<<<MT * NT, 256, SMEM_TOTAL>>>(b, out);   // 256 CTAs
}

// round 6
// speedup vs baseline: 3.1106x; 1.0621x over previous
#include <cuda_runtime.h>
#include <cuda_fp16.h>
#include <math.h>
#include <stdint.h>

#define N_TOKENS 8192
#define D_IN     1024
#define D_OUT    1024
#define N_EXP    8

#define BM 128
#define BN 128
#define KCH 32                   // k-chunks per expert (BK=32)
#define MT  (N_TOKENS / BM)      // 64
#define NT  (D_OUT / BN)         // 8
#define ITERS (N_EXP * KCH)      // 256
#define NSTAGE 3

#define A_TILE_BYTES 8192        // 128 x 32 fp16, fragment-packed
#define B_TILE_BYTES 8192        // 32 x 128 fp16, fragment-packed
#define STAGE_BYTES  (A_TILE_BYTES + B_TILE_BYTES)     // 16384
#define SMEM_G   (NSTAGE * STAGE_BYTES)                // 49152 : gate 128x8 f32
#define SMEM_BS  (SMEM_G + 4096)                       // 53248 : bias 8x128 f32
#define SMEM_TOTAL (SMEM_BS + 4096)                    // 57344

// ---------------------------------------------------------------------------
// scratch (device globals: no allocation allowed)
// ---------------------------------------------------------------------------
__device__ float  g_gate[N_TOKENS * N_EXP];
__device__ __half x_pack[(size_t)MT * KCH * 4096];           // 16 MB (ungated)
__device__ __half w_pack[(size_t)N_EXP * NT * KCH * 4096];   // 16 MB

// ---------------------------------------------------------------------------
// helpers
// ---------------------------------------------------------------------------
__device__ __forceinline__ uint32_t smem_u32(const void* p) {
    uint32_t a;
    asm("{ .reg .u64 t; cvta.to.shared.u64 t, %1; cvt.u32.u64 %0, t; }" : "=r"(a) : "l"(p));
    return a;
}
__device__ __forceinline__ void cp16(uint32_t d, const void* s) {
    asm volatile("cp.async.cg.shared.global [%0], [%1], 16;" :: "r"(d), "l"(s));
}
__device__ __forceinline__ void cp_commit() {
    asm volatile("cp.async.commit_group;" ::: "memory");
}
__device__ __forceinline__ void cp_wait1() {
    asm volatile("cp.async.wait_group 1;" ::: "memory");
}
__device__ __forceinline__ void mma_f16(float* d, const uint32_t* a,
                                        const uint32_t* b, const float* c) {
    asm volatile(
        "mma.sync.aligned.m16n8k16.row.col.f32.f16.f16.f32 "
        "{%0,%1,%2,%3}, {%4,%5,%6,%7}, {%8,%9}, {%10,%11,%12,%13};\n"
        : "=f"(d[0]), "=f"(d[1]), "=f"(d[2]), "=f"(d[3])
        : "r"(a[0]), "r"(a[1]), "r"(a[2]), "r"(a[3]),
          "r"(b[0]), "r"(b[1]),
          "f"(c[0]), "f"(c[1]), "f"(c[2]), "f"(c[3]));
}
__device__ __forceinline__ uint32_t h2u(float lo, float hi) {
    __half2 h = __halves2half2(__float2half_rn(lo), __float2half_rn(hi));
    return *reinterpret_cast<uint32_t*>(&h);
}
__device__ __forceinline__ uint32_t hmul2u(uint32_t a, uint32_t g) {
    __half2 r = __hmul2(*reinterpret_cast<__half2*>(&a), *reinterpret_cast<__half2*>(&g));
    return *reinterpret_cast<uint32_t*>(&r);
}

// ---------------------------------------------------------------------------
// Gate: g = softmax(x @ gate_W + gate_b), one warp per token
// ---------------------------------------------------------------------------
__global__ void gate_kernel(const float* __restrict__ x,
                            const float* __restrict__ gate_W,
                            const float* __restrict__ gate_b) {
    int warp = threadIdx.x >> 5, lane = threadIdx.x & 31;
    int token = blockIdx.x * 8 + warp;
    if (token >= N_TOKENS) return;
    const float* xr = x + (size_t)token * D_IN;
    float acc[N_EXP];
#pragma unroll
    for (int e = 0; e < N_EXP; e++) acc[e] = 0.f;
    for (int i = lane; i < D_IN; i += 32) {
        float xv = xr[i];
        const float4* gw = reinterpret_cast<const float4*>(gate_W + (size_t)i * N_EXP);
        float4 w0 = gw[0], w1 = gw[1];
        acc[0] += xv * w0.x; acc[1] += xv * w0.y; acc[2] += xv * w0.z; acc[3] += xv * w0.w;
        acc[4] += xv * w1.x; acc[5] += xv * w1.y; acc[6] += xv * w1.z; acc[7] += xv * w1.w;
    }
#pragma unroll
    for (int e = 0; e < N_EXP; e++)
#pragma unroll
        for (int o = 16; o > 0; o >>= 1)
            acc[e] += __shfl_xor_sync(0xffffffffu, acc[e], o);
    if (lane == 0) {
        float m = -1e30f;
#pragma unroll
        for (int e = 0; e < N_EXP; e++) { acc[e] += gate_b[e]; m = fmaxf(m, acc[e]); }
        float s = 0.f;
#pragma unroll
        for (int e = 0; e < N_EXP; e++) { acc[e] = expf(acc[e] - m); s += acc[e]; }
        float inv = 1.f / s;
#pragma unroll
        for (int e = 0; e < N_EXP; e++) g_gate[token * N_EXP + e] = acc[e] * inv;
    }
}

// ---------------------------------------------------------------------------
// pack_x: x_pack[mt][kc] = 128x32 tile of x, fp16, m16n8k16 A-fragment layout.
// Entry (ks2 0..1, m16 0..7, lane) = {a0,a1,a2,a3} packed half2s.
// ---------------------------------------------------------------------------
__global__ void pack_x_kernel(const float* __restrict__ x) {
    __shared__ float xs[128 * 36];
    const int blk = blockIdx.x;                  // mt*32 + kc
    const int kc = blk & 31, mt = blk >> 5;
    const int tid = threadIdx.x;

    const float* src = x + (size_t)(mt * BM) * D_IN + kc * 32;
    for (int idx = tid; idx < 1024; idx += 256) {
        int row = idx >> 3, c4 = idx & 7;
        float4 v = *reinterpret_cast<const float4*>(src + (size_t)row * D_IN + c4 * 4);
        *reinterpret_cast<float4*>(xs + row * 36 + c4 * 4) = v;
    }
    __syncthreads();

    __half* dst = x_pack + (size_t)blk * 4096;
#pragma unroll
    for (int q = 0; q < 2; q++) {
        int ent = tid + q * 256;                 // 0..511
        int lane = ent & 31, m16 = (ent >> 5) & 7, ks2 = ent >> 8;
        int gid = lane >> 2, tig = lane & 3;
        int r0 = m16 * 16 + gid, r1 = r0 + 8, c0 = ks2 * 16 + 2 * tig;
        const float* x0 = xs + r0 * 36;
        const float* x1 = xs + r1 * 36;
        uint4 w;
        w.x = h2u(x0[c0],     x0[c0 + 1]);
        w.y = h2u(x1[c0],     x1[c0 + 1]);
        w.z = h2u(x0[c0 + 8], x0[c0 + 9]);
        w.w = h2u(x1[c0 + 8], x1[c0 + 9]);
        *reinterpret_cast<uint4*>(dst + ent * 8) = w;
    }
}

// ---------------------------------------------------------------------------
// pack_w: w_pack[e][nt][kc] = 32(k)x128(n) tile of W^T, fp16, B-fragment layout.
// ---------------------------------------------------------------------------
__global__ void pack_w_kernel(const float* __restrict__ W) {
    __shared__ float ws[32 * 132];
    const int blk = blockIdx.x;                  // e*256 + nt*32 + kc
    const int kc = blk & 31, nt = (blk >> 5) & 7, e = blk >> 8;
    const int tid = threadIdx.x;

    const float* src = W + ((size_t)e * D_IN + kc * 32) * D_OUT + nt * 128;
    for (int idx = tid; idx < 1024; idx += 256) {
        int il = idx >> 5, o4 = idx & 31;
        float4 v = *reinterpret_cast<const float4*>(src + (size_t)il * D_OUT + o4 * 4);
        *reinterpret_cast<float4*>(ws + il * 132 + o4 * 4) = v;
    }
    __syncthreads();

    __half* dst = w_pack + (size_t)blk * 4096;
#pragma unroll
    for (int q = 0; q < 2; q++) {
        int ent = tid + q * 256;                 // 0..511
        int lane = ent & 31, jp = (ent >> 5) & 7, ks2 = ent >> 8;
        int gid = lane >> 2, tig = lane & 3;
        int kr = ks2 * 16 + 2 * tig;
        int cA = jp * 16 + gid, cB = cA + 8;
        uint4 w;
        w.x = h2u(ws[kr * 132 + cA],       ws[(kr + 1) * 132 + cA]);
        w.y = h2u(ws[(kr + 8) * 132 + cA], ws[(kr + 9) * 132 + cA]);
        w.z = h2u(ws[kr * 132 + cB],       ws[(kr + 1) * 132 + cB]);
        w.w = h2u(ws[(kr + 8) * 132 + cB], ws[(kr + 9) * 132 + cB]);
        *reinterpret_cast<uint4*>(dst + ent * 8) = w;
    }
}

// ---------------------------------------------------------------------------
// Hot GEMM: 128x128 tile, 8 warps 2(m) x 4(n), warp tile 64x32, occupancy 2.
// A ungated in SMEM; gate applied to A fragments in registers (HMUL2).
// ---------------------------------------------------------------------------
__global__ void __launch_bounds__(256, 2)
moe_mma_kernel(const float* __restrict__ bias, float* __restrict__ out) {
    extern __shared__ char smem[];
    const int tid = threadIdx.x, wid = tid >> 5, lane = tid & 31;
    const int gid = lane >> 2, tig = lane & 3;
    const int wm = wid >> 2, wn = wid & 3;
    const int nt = blockIdx.x & 7, mt = blockIdx.x >> 3;
    const int m0 = mt * BM, n0 = nt * BN;
    const uint32_t sb = smem_u32(smem);

    float* g_s = reinterpret_cast<float*>(smem + SMEM_G);
    float* b_s = reinterpret_cast<float*>(smem + SMEM_BS);
    for (int i = tid; i < BM * N_EXP; i += 256) g_s[i] = g_gate[m0 * N_EXP + i];
    for (int i = tid; i < N_EXP * BN; i += 256)
        b_s[i] = bias[(size_t)(i >> 7) * D_OUT + n0 + (i & 127)];

    float acc[4][4][4];
#pragma unroll
    for (int a = 0; a < 4; a++)
#pragma unroll
        for (int b = 0; b < 4; b++)
#pragma unroll
            for (int c = 0; c < 4; c++) acc[a][b][c] = 0.f;

    auto issue = [&](int it, int buf) {
        const int e = it >> 5, kc = it & 31;
        const char* asrc = (const char*)(x_pack + (size_t)(mt * KCH + kc) * 4096);
        const char* bsrc = (const char*)(w_pack + (size_t)((e * NT + nt) * KCH + kc) * 4096);
        uint32_t d = sb + buf * STAGE_BYTES + tid * 16;
        cp16(d,         asrc + tid * 16);
        cp16(d + 4096,  asrc + tid * 16 + 4096);
        cp16(d + 8192,  bsrc + tid * 16);
        cp16(d + 12288, bsrc + tid * 16 + 4096);
        cp_commit();
    };

    issue(0, 0);
    issue(1, 1);

    // RACE FIX (R5 bug): publish g_s/b_s to ALL threads before any thread
    // reads gate rows written by other warps.
    __syncthreads();

    // per-thread gate half2s for this thread's 8 A-fragment rows (updated per expert)
    uint32_t g2[4][2];

    for (int e = 0; e < N_EXP; e++) {
#pragma unroll
        for (int mtt = 0; mtt < 4; mtt++) {
            int r0 = wm * 64 + mtt * 16 + gid;
            float gv0 = g_s[r0 * N_EXP + e];
            float gv1 = g_s[(r0 + 8) * N_EXP + e];
            g2[mtt][0] = h2u(gv0, gv0);
            g2[mtt][1] = h2u(gv1, gv1);
        }
        for (int kc = 0; kc < KCH; kc++) {
            const int it = e * KCH + kc;
            cp_wait1();                 // stage it landed
            __syncthreads();            // publish; stage it-1 fully consumed
            if (it + 2 < ITERS) issue(it + 2, (it + 2) % NSTAGE);

            const char* ab = smem + (it % NSTAGE) * STAGE_BYTES;
            const char* bb = ab + A_TILE_BYTES;
#pragma unroll
            for (int ks2 = 0; ks2 < 2; ks2++) {
                uint4 af[4], bf[2];
#pragma unroll
                for (int mtt = 0; mtt < 4; mtt++) {
                    af[mtt] = *reinterpret_cast<const uint4*>(
                        ab + (size_t)((ks2 * 8 + wm * 4 + mtt) * 32 + lane) * 16);
                    af[mtt].x = hmul2u(af[mtt].x, g2[mtt][0]);
                    af[mtt].y = hmul2u(af[mtt].y, g2[mtt][1]);
                    af[mtt].z = hmul2u(af[mtt].z, g2[mtt][0]);
                    af[mtt].w = hmul2u(af[mtt].w, g2[mtt][1]);
                }
#pragma unroll
                for (int jpi = 0; jpi < 2; jpi++)
                    bf[jpi] = *reinterpret_cast<const uint4*>(
                        bb + (size_t)((ks2 * 8 + wn * 2 + jpi) * 32 + lane) * 16);
#pragma unroll
                for (int mtt = 0; mtt < 4; mtt++)
#pragma unroll
                    for (int ntt = 0; ntt < 4; ntt++) {
                        const uint32_t* a = reinterpret_cast<const uint32_t*>(&af[mtt]);
                        const uint32_t* bp =
                            reinterpret_cast<const uint32_t*>(&bf[ntt >> 1]) + (ntt & 1) * 2;
                        mma_f16(acc[mtt][ntt], a, bp, acc[mtt][ntt]);
                    }
            }
        }
    }

    // ---- epilogue: gated bias + store ----
#pragma unroll
    for (int mtt = 0; mtt < 4; mtt++) {
        const int rb = wm * 64 + mtt * 16 + gid;
#pragma unroll
        for (int half = 0; half < 2; half++) {
            const int r = rb + half * 8;
            const float* gr = g_s + r * N_EXP;
            float* orow = out + (size_t)(m0 + r) * D_OUT + n0;
#pragma unroll
            for (int ntt = 0; ntt < 4; ntt++) {
                const int c = wn * 32 + ntt * 8 + 2 * tig;
                float b0 = 0.f, b1 = 0.f;
#pragma unroll
                for (int e = 0; e < N_EXP; e++) {
                    float gv = gr[e];
                    b0 += gv * b_s[e * BN + c];
                    b1 += gv * b_s[e * BN + c + 1];
                }
                float2 v;
                v.x = acc[mtt][ntt][half * 2 + 0] + b0;
                v.y = acc[mtt][ntt][half * 2 + 1] + b1;
                *reinterpret_cast<float2*>(orow + c) = v;
            }
        }
    }
}

// ---------------------------------------------------------------------------
extern "C" void kernel_launch(void* const* d_in, const int* in_sizes, int n_in,
                              void* d_out, int out_size) {
    const float* x      = (const float*)d_in[0];
    const float* W      = (const float*)d_in[1];
    const float* b      = (const float*)d_in[2];
    const float* gate_W = (const float*)d_in[3];
    const float* gate_b = (const float*)d_in[4];
    float* out = (float*)d_out;

    gate_kernel<<<N_TOKENS / 8, 256>>>(x, gate_W, gate_b);
    pack_x_kernel<<<MT * KCH, 256>>>(x);           // 2048 blocks
    pack_w_kernel<<<N_EXP * NT * KCH, 256>>>(W);   // 2048 blocks

    cudaFuncSetAttribute(moe_mma_kernel,
                         cudaFuncAttributeMaxDynamicSharedMemorySize, SMEM_TOTAL);
    moe_mma_kernel<<<MT * NT, 256, SMEM_TOTAL>>>(b, out);   // 512 CTAs
}

// round 7
// speedup vs baseline: 3.5352x; 1.1365x over previous
#include <cuda_runtime.h>
#include <cuda_fp16.h>
#include <math.h>
#include <stdint.h>

#define N_TOKENS 8192
#define D_IN     1024
#define D_OUT    1024
#define N_EXP    8

#define BM 128
#define BN 128
#define BK 64                    // floats per k-chunk
#define KCH (D_IN / BK)          // 16 chunks per expert
#define MT  (N_TOKENS / BM)      // 64
#define NT  (D_OUT / BN)         // 8
#define ITERS (N_EXP * KCH)      // 128
#define NSTAGE 3
#define NTHREADS 128

#define A_TILE_BYTES 16384       // 128 x 64 fp16, fragment-packed
#define B_TILE_BYTES 16384       // 64 x 128 fp16, fragment-packed
#define STAGE_BYTES  (A_TILE_BYTES + B_TILE_BYTES)     // 32768
#define SMEM_G   (NSTAGE * STAGE_BYTES)                // 98304 : gate 128x8 f32
#define SMEM_BS  (SMEM_G + 4096)                       // 102400: bias 8x128 f32
#define SMEM_TOTAL (SMEM_BS + 4096)                    // 106496 per CTA (x2 = 208K < 228K)

// ---------------------------------------------------------------------------
// scratch (device globals: no allocation allowed)
// ---------------------------------------------------------------------------
__device__ float  g_gate[N_TOKENS * N_EXP];
__device__ __half x_pack[(size_t)MT * KCH * 8192];           // 16 MB (ungated)
__device__ __half w_pack[(size_t)N_EXP * NT * KCH * 8192];   // 16 MB

// ---------------------------------------------------------------------------
// helpers
// ---------------------------------------------------------------------------
__device__ __forceinline__ uint32_t smem_u32(const void* p) {
    uint32_t a;
    asm("{ .reg .u64 t; cvta.to.shared.u64 t, %1; cvt.u32.u64 %0, t; }" : "=r"(a) : "l"(p));
    return a;
}
__device__ __forceinline__ void cp16(uint32_t d, const void* s) {
    asm volatile("cp.async.cg.shared.global [%0], [%1], 16;" :: "r"(d), "l"(s));
}
__device__ __forceinline__ void cp_commit() {
    asm volatile("cp.async.commit_group;" ::: "memory");
}
__device__ __forceinline__ void cp_wait1() {
    asm volatile("cp.async.wait_group 1;" ::: "memory");
}
__device__ __forceinline__ void mma_f16(float* d, const uint32_t* a,
                                        const uint32_t* b, const float* c) {
    asm volatile(
        "mma.sync.aligned.m16n8k16.row.col.f32.f16.f16.f32 "
        "{%0,%1,%2,%3}, {%4,%5,%6,%7}, {%8,%9}, {%10,%11,%12,%13};\n"
        : "=f"(d[0]), "=f"(d[1]), "=f"(d[2]), "=f"(d[3])
        : "r"(a[0]), "r"(a[1]), "r"(a[2]), "r"(a[3]),
          "r"(b[0]), "r"(b[1]),
          "f"(c[0]), "f"(c[1]), "f"(c[2]), "f"(c[3]));
}
__device__ __forceinline__ uint32_t h2u(float lo, float hi) {
    __half2 h = __halves2half2(__float2half_rn(lo), __float2half_rn(hi));
    return *reinterpret_cast<uint32_t*>(&h);
}
__device__ __forceinline__ uint32_t hmul2u(uint32_t a, uint32_t g) {
    __half2 r = __hmul2(*reinterpret_cast<__half2*>(&a), *reinterpret_cast<__half2*>(&g));
    return *reinterpret_cast<uint32_t*>(&r);
}

// ---------------------------------------------------------------------------
// Gate: g = softmax(x @ gate_W + gate_b), one warp per token
// ---------------------------------------------------------------------------
__global__ void gate_kernel(const float* __restrict__ x,
                            const float* __restrict__ gate_W,
                            const float* __restrict__ gate_b) {
    int warp = threadIdx.x >> 5, lane = threadIdx.x & 31;
    int token = blockIdx.x * 8 + warp;
    if (token >= N_TOKENS) return;
    const float* xr = x + (size_t)token * D_IN;
    float acc[N_EXP];
#pragma unroll
    for (int e = 0; e < N_EXP; e++) acc[e] = 0.f;
    for (int i = lane; i < D_IN; i += 32) {
        float xv = xr[i];
        const float4* gw = reinterpret_cast<const float4*>(gate_W + (size_t)i * N_EXP);
        float4 w0 = gw[0], w1 = gw[1];
        acc[0] += xv * w0.x; acc[1] += xv * w0.y; acc[2] += xv * w0.z; acc[3] += xv * w0.w;
        acc[4] += xv * w1.x; acc[5] += xv * w1.y; acc[6] += xv * w1.z; acc[7] += xv * w1.w;
    }
#pragma unroll
    for (int e = 0; e < N_EXP; e++)
#pragma unroll
        for (int o = 16; o > 0; o >>= 1)
            acc[e] += __shfl_xor_sync(0xffffffffu, acc[e], o);
    if (lane == 0) {
        float m = -1e30f;
#pragma unroll
        for (int e = 0; e < N_EXP; e++) { acc[e] += gate_b[e]; m = fmaxf(m, acc[e]); }
        float s = 0.f;
#pragma unroll
        for (int e = 0; e < N_EXP; e++) { acc[e] = expf(acc[e] - m); s += acc[e]; }
        float inv = 1.f / s;
#pragma unroll
        for (int e = 0; e < N_EXP; e++) g_gate[token * N_EXP + e] = acc[e] * inv;
    }
}

// ---------------------------------------------------------------------------
// pack_x: x_pack[mt][kc] = 128x64 tile of x, fp16, m16n8k16 A-fragment layout.
// Entry (ks2 0..3, m16 0..7, lane) = {a0,a1,a2,a3} packed half2s.
// ---------------------------------------------------------------------------
__global__ void pack_x_kernel(const float* __restrict__ x) {
    __shared__ float xs[128 * 68];
    const int blk = blockIdx.x;                  // mt*16 + kc
    const int kc = blk & 15, mt = blk >> 4;
    const int tid = threadIdx.x;

    const float* src = x + (size_t)(mt * BM) * D_IN + kc * BK;
    for (int idx = tid; idx < 2048; idx += 256) {
        int row = idx >> 4, c4 = idx & 15;
        float4 v = *reinterpret_cast<const float4*>(src + (size_t)row * D_IN + c4 * 4);
        *reinterpret_cast<float4*>(xs + row * 68 + c4 * 4) = v;
    }
    __syncthreads();

    __half* dst = x_pack + (size_t)blk * 8192;
#pragma unroll
    for (int q = 0; q < 4; q++) {
        int ent = tid + q * 256;                 // 0..1023
        int lane = ent & 31, m16 = (ent >> 5) & 7, ks2 = ent >> 8;
        int gid = lane >> 2, tig = lane & 3;
        int r0 = m16 * 16 + gid, r1 = r0 + 8, c0 = ks2 * 16 + 2 * tig;
        const float* x0 = xs + r0 * 68;
        const float* x1 = xs + r1 * 68;
        uint4 w;
        w.x = h2u(x0[c0],     x0[c0 + 1]);
        w.y = h2u(x1[c0],     x1[c0 + 1]);
        w.z = h2u(x0[c0 + 8], x0[c0 + 9]);
        w.w = h2u(x1[c0 + 8], x1[c0 + 9]);
        *reinterpret_cast<uint4*>(dst + ent * 8) = w;
    }
}

// ---------------------------------------------------------------------------
// pack_w: w_pack[e][nt][kc] = 64(k)x128(n) tile of W^T, fp16, B-fragment layout.
// Entry (ks2 0..3, jp 0..7, lane) = {b0(j0),b1(j0),b0(j1),b1(j1)} packed half2s.
// ---------------------------------------------------------------------------
__global__ void pack_w_kernel(const float* __restrict__ W) {
    __shared__ float ws[64 * 132];
    const int blk = blockIdx.x;                  // (e*NT+nt)*16 + kc
    const int kc = blk & 15, nt = (blk >> 4) & 7, e = blk >> 7;
    const int tid = threadIdx.x;

    const float* src = W + ((size_t)e * D_IN + kc * BK) * D_OUT + nt * 128;
    for (int idx = tid; idx < 2048; idx += 256) {
        int il = idx >> 5, o4 = idx & 31;
        float4 v = *reinterpret_cast<const float4*>(src + (size_t)il * D_OUT + o4 * 4);
        *reinterpret_cast<float4*>(ws + il * 132 + o4 * 4) = v;
    }
    __syncthreads();

    __half* dst = w_pack + (size_t)blk * 8192;
#pragma unroll
    for (int q = 0; q < 4; q++) {
        int ent = tid + q * 256;                 // 0..1023
        int lane = ent & 31, jp = (ent >> 5) & 7, ks2 = ent >> 8;
        int gid = lane >> 2, tig = lane & 3;
        int kr = ks2 * 16 + 2 * tig;
        int cA = jp * 16 + gid, cB = cA + 8;
        uint4 w;
        w.x = h2u(ws[kr * 132 + cA],       ws[(kr + 1) * 132 + cA]);
        w.y = h2u(ws[(kr + 8) * 132 + cA], ws[(kr + 9) * 132 + cA]);
        w.z = h2u(ws[kr * 132 + cB],       ws[(kr + 1) * 132 + cB]);
        w.w = h2u(ws[(kr + 8) * 132 + cB], ws[(kr + 9) * 132 + cB]);
        *reinterpret_cast<uint4*>(dst + ent * 8) = w;
    }
}

// ---------------------------------------------------------------------------
// Hot GEMM: 128x128 CTA tile, 4 warps 2(m) x 2(n), warp tile 64x64, occ 2.
// BK=64 (4 ks2 per iter), 3-stage cp.async pipeline, one barrier per iter.
// A ungated in SMEM; gate applied to A fragments in registers (HMUL2).
// ---------------------------------------------------------------------------
__global__ void __launch_bounds__(NTHREADS, 2)
moe_mma_kernel(const float* __restrict__ bias, float* __restrict__ out) {
    extern __shared__ char smem[];
    const int tid = threadIdx.x, wid = tid >> 5, lane = tid & 31;
    const int gid = lane >> 2, tig = lane & 3;
    const int wm = wid >> 1, wn = wid & 1;
    const int nt = blockIdx.x & 7, mt = blockIdx.x >> 3;
    const int m0 = mt * BM, n0 = nt * BN;
    const uint32_t sb = smem_u32(smem);

    float* g_s = reinterpret_cast<float*>(smem + SMEM_G);
    float* b_s = reinterpret_cast<float*>(smem + SMEM_BS);
    for (int i = tid; i < BM * N_EXP; i += NTHREADS) g_s[i] = g_gate[m0 * N_EXP + i];
    for (int i = tid; i < N_EXP * BN; i += NTHREADS)
        b_s[i] = bias[(size_t)(i >> 7) * D_OUT + n0 + (i & 127)];

    float acc[4][8][4];
#pragma unroll
    for (int a = 0; a < 4; a++)
#pragma unroll
        for (int b = 0; b < 8; b++)
#pragma unroll
            for (int c = 0; c < 4; c++) acc[a][b][c] = 0.f;

    auto issue = [&](int it, int buf) {
        const int e = it >> 4, kc = it & 15;
        const char* asrc = (const char*)(x_pack + (size_t)(mt * KCH + kc) * 8192);
        const char* bsrc = (const char*)(w_pack + (size_t)((e * NT + nt) * KCH + kc) * 8192);
        uint32_t d = sb + buf * STAGE_BYTES + tid * 16;
#pragma unroll
        for (int r = 0; r < 8; r++) cp16(d + r * 2048, asrc + tid * 16 + r * 2048);
#pragma unroll
        for (int r = 0; r < 8; r++)
            cp16(d + A_TILE_BYTES + r * 2048, bsrc + tid * 16 + r * 2048);
        cp_commit();
    };

    issue(0, 0);
    issue(1, 1);

    // publish g_s/b_s to all threads before any cross-warp read (R5 race fix)
    __syncthreads();

    // per-thread gate half2s for this thread's 8 A-fragment rows, per expert
    uint32_t g2[4][2];

    for (int e = 0; e < N_EXP; e++) {
#pragma unroll
        for (int mtt = 0; mtt < 4; mtt++) {
            int r0 = wm * 64 + mtt * 16 + gid;
            float gv0 = g_s[r0 * N_EXP + e];
            float gv1 = g_s[(r0 + 8) * N_EXP + e];
            g2[mtt][0] = h2u(gv0, gv0);
            g2[mtt][1] = h2u(gv1, gv1);
        }
        for (int kc = 0; kc < KCH; kc++) {
            const int it = e * KCH + kc;
            cp_wait1();                 // stage `it` landed
            __syncthreads();            // publish; stage it-1 fully consumed
            if (it + 2 < ITERS) issue(it + 2, (it + 2) % NSTAGE);

            const char* ab = smem + (it % NSTAGE) * STAGE_BYTES;
            const char* bb = ab + A_TILE_BYTES;
#pragma unroll
            for (int ks2 = 0; ks2 < 4; ks2++) {
                uint4 af[4], bf[4];
#pragma unroll
                for (int mtt = 0; mtt < 4; mtt++) {
                    af[mtt] = *reinterpret_cast<const uint4*>(
                        ab + (size_t)((ks2 * 8 + wm * 4 + mtt) * 32 + lane) * 16);
                    af[mtt].x = hmul2u(af[mtt].x, g2[mtt][0]);
                    af[mtt].y = hmul2u(af[mtt].y, g2[mtt][1]);
                    af[mtt].z = hmul2u(af[mtt].z, g2[mtt][0]);
                    af[mtt].w = hmul2u(af[mtt].w, g2[mtt][1]);
                }
#pragma unroll
                for (int jpi = 0; jpi < 4; jpi++)
                    bf[jpi] = *reinterpret_cast<const uint4*>(
                        bb + (size_t)((ks2 * 8 + wn * 4 + jpi) * 32 + lane) * 16);
#pragma unroll
                for (int mtt = 0; mtt < 4; mtt++)
#pragma unroll
                    for (int ntt = 0; ntt < 8; ntt++) {
                        const uint32_t* a = reinterpret_cast<const uint32_t*>(&af[mtt]);
                        const uint32_t* bp =
                            reinterpret_cast<const uint32_t*>(&bf[ntt >> 1]) + (ntt & 1) * 2;
                        mma_f16(acc[mtt][ntt], a, bp, acc[mtt][ntt]);
                    }
            }
        }
    }

    // ---- epilogue: gated bias + store ----
#pragma unroll
    for (int mtt = 0; mtt < 4; mtt++) {
        const int rb = wm * 64 + mtt * 16 + gid;
#pragma unroll
        for (int half = 0; half < 2; half++) {
            const int r = rb + half * 8;
            const float* gr = g_s + r * N_EXP;
            float* orow = out + (size_t)(m0 + r) * D_OUT + n0;
#pragma unroll
            for (int ntt = 0; ntt < 8; ntt++) {
                const int c = wn * 64 + ntt * 8 + 2 * tig;
                float b0 = 0.f, b1 = 0.f;
#pragma unroll
                for (int e = 0; e < N_EXP; e++) {
                    float gv = gr[e];
                    b0 += gv * b_s[e * BN + c];
                    b1 += gv * b_s[e * BN + c + 1];
                }
                float2 v;
                v.x = acc[mtt][ntt][half * 2 + 0] + b0;
                v.y = acc[mtt][ntt][half * 2 + 1] + b1;
                *reinterpret_cast<float2*>(orow + c) = v;
            }
        }
    }
}

// ---------------------------------------------------------------------------
extern "C" void kernel_launch(void* const* d_in, const int* in_sizes, int n_in,
                              void* d_out, int out_size) {
    const float* x      = (const float*)d_in[0];
    const float* W      = (const float*)d_in[1];
    const float* b      = (const float*)d_in[2];
    const float* gate_W = (const float*)d_in[3];
    const float* gate_b = (const float*)d_in[4];
    float* out = (float*)d_out;

    gate_kernel<<<N_TOKENS / 8, 256>>>(x, gate_W, gate_b);
    pack_x_kernel<<<MT * KCH, 256>>>(x);           // 1024 blocks
    pack_w_kernel<<<N_EXP * NT * KCH, 256>>>(W);   // 1024 blocks

    cudaFuncSetAttribute(moe_mma_kernel,
                         cudaFuncAttributeMaxDynamicSharedMemorySize, SMEM_TOTAL);
    moe_mma_kernel<<<MT * NT, NTHREADS, SMEM_TOTAL>>>(b, out);   // 512 CTAs
}

// round 8
// speedup vs baseline: 3.5415x; 1.0018x over previous
#include <cuda_runtime.h>
#include <cuda_fp16.h>
#include <math.h>
#include <stdint.h>

#define N_TOKENS 8192
#define D_IN     1024
#define D_OUT    1024
#define N_EXP    8

#define BM 128
#define BN 128
#define BK 64                    // floats per k-chunk
#define KCH (D_IN / BK)          // 16 chunks per expert
#define MT  (N_TOKENS / BM)      // 64
#define NT  (D_OUT / BN)         // 8
#define ITERS (N_EXP * KCH)      // 128
#define NSTAGE 3
#define NTHREADS 128

#define A_TILE_BYTES 16384       // 128 x 64 fp16, fragment-packed
#define B_TILE_BYTES 16384       // 64 x 128 fp16, fragment-packed
#define STAGE_BYTES  (A_TILE_BYTES + B_TILE_BYTES)     // 32768
#define SMEM_G   (NSTAGE * STAGE_BYTES)                // 98304 : gate 128x8 f32
#define SMEM_BS  (SMEM_G + 4096)                       // 102400: bias 8x128 f32
#define SMEM_TOTAL (SMEM_BS + 4096)                    // 106496 per CTA (x2 = 208K < 228K)

// ---------------------------------------------------------------------------
// scratch (device globals: no allocation allowed)
// ---------------------------------------------------------------------------
__device__ float  g_gate[N_TOKENS * N_EXP];
__device__ __half x_pack[(size_t)MT * KCH * 8192];           // 16 MB (ungated)
__device__ __half w_pack[(size_t)N_EXP * NT * KCH * 8192];   // 16 MB

// ---------------------------------------------------------------------------
// helpers
// ---------------------------------------------------------------------------
__device__ __forceinline__ uint32_t smem_u32(const void* p) {
    uint32_t a;
    asm("{ .reg .u64 t; cvta.to.shared.u64 t, %1; cvt.u32.u64 %0, t; }" : "=r"(a) : "l"(p));
    return a;
}
__device__ __forceinline__ void cp16(uint32_t d, const void* s) {
    asm volatile("cp.async.cg.shared.global [%0], [%1], 16;" :: "r"(d), "l"(s));
}
__device__ __forceinline__ void cp_commit() {
    asm volatile("cp.async.commit_group;" ::: "memory");
}
__device__ __forceinline__ void cp_wait1() {
    asm volatile("cp.async.wait_group 1;" ::: "memory");
}
__device__ __forceinline__ void mma_f16(float* d, const uint32_t* a,
                                        const uint32_t* b, const float* c) {
    asm volatile(
        "mma.sync.aligned.m16n8k16.row.col.f32.f16.f16.f32 "
        "{%0,%1,%2,%3}, {%4,%5,%6,%7}, {%8,%9}, {%10,%11,%12,%13};\n"
        : "=f"(d[0]), "=f"(d[1]), "=f"(d[2]), "=f"(d[3])
        : "r"(a[0]), "r"(a[1]), "r"(a[2]), "r"(a[3]),
          "r"(b[0]), "r"(b[1]),
          "f"(c[0]), "f"(c[1]), "f"(c[2]), "f"(c[3]));
}
__device__ __forceinline__ uint32_t h2u(float lo, float hi) {
    __half2 h = __halves2half2(__float2half_rn(lo), __float2half_rn(hi));
    return *reinterpret_cast<uint32_t*>(&h);
}
__device__ __forceinline__ uint32_t hmul2u(uint32_t a, uint32_t g) {
    __half2 r = __hmul2(*reinterpret_cast<__half2*>(&a), *reinterpret_cast<__half2*>(&g));
    return *reinterpret_cast<uint32_t*>(&r);
}

// ---------------------------------------------------------------------------
// Gate: g = softmax(x @ gate_W + gate_b), one warp per token
// ---------------------------------------------------------------------------
__global__ void gate_kernel(const float* __restrict__ x,
                            const float* __restrict__ gate_W,
                            const float* __restrict__ gate_b) {
    int warp = threadIdx.x >> 5, lane = threadIdx.x & 31;
    int token = blockIdx.x * 8 + warp;
    if (token >= N_TOKENS) return;
    const float* xr = x + (size_t)token * D_IN;
    float acc[N_EXP];
#pragma unroll
    for (int e = 0; e < N_EXP; e++) acc[e] = 0.f;
    for (int i = lane; i < D_IN; i += 32) {
        float xv = xr[i];
        const float4* gw = reinterpret_cast<const float4*>(gate_W + (size_t)i * N_EXP);
        float4 w0 = gw[0], w1 = gw[1];
        acc[0] += xv * w0.x; acc[1] += xv * w0.y; acc[2] += xv * w0.z; acc[3] += xv * w0.w;
        acc[4] += xv * w1.x; acc[5] += xv * w1.y; acc[6] += xv * w1.z; acc[7] += xv * w1.w;
    }
#pragma unroll
    for (int e = 0; e < N_EXP; e++)
#pragma unroll
        for (int o = 16; o > 0; o >>= 1)
            acc[e] += __shfl_xor_sync(0xffffffffu, acc[e], o);
    if (lane == 0) {
        float m = -1e30f;
#pragma unroll
        for (int e = 0; e < N_EXP; e++) { acc[e] += gate_b[e]; m = fmaxf(m, acc[e]); }
        float s = 0.f;
#pragma unroll
        for (int e = 0; e < N_EXP; e++) { acc[e] = expf(acc[e] - m); s += acc[e]; }
        float inv = 1.f / s;
#pragma unroll
        for (int e = 0; e < N_EXP; e++) g_gate[token * N_EXP + e] = acc[e] * inv;
    }
}

// ---------------------------------------------------------------------------
// pack_x: x_pack[mt][kc] = 128x64 tile of x, fp16, m16n8k16 A-fragment layout.
// Entry (ks2 0..3, m16 0..7, lane) = {a0,a1,a2,a3} packed half2s.
// ---------------------------------------------------------------------------
__global__ void pack_x_kernel(const float* __restrict__ x) {
    __shared__ float xs[128 * 68];
    const int blk = blockIdx.x;                  // mt*16 + kc
    const int kc = blk & 15, mt = blk >> 4;
    const int tid = threadIdx.x;

    const float* src = x + (size_t)(mt * BM) * D_IN + kc * BK;
    for (int idx = tid; idx < 2048; idx += 256) {
        int row = idx >> 4, c4 = idx & 15;
        float4 v = *reinterpret_cast<const float4*>(src + (size_t)row * D_IN + c4 * 4);
        *reinterpret_cast<float4*>(xs + row * 68 + c4 * 4) = v;
    }
    __syncthreads();

    __half* dst = x_pack + (size_t)blk * 8192;
#pragma unroll
    for (int q = 0; q < 4; q++) {
        int ent = tid + q * 256;                 // 0..1023
        int lane = ent & 31, m16 = (ent >> 5) & 7, ks2 = ent >> 8;
        int gid = lane >> 2, tig = lane & 3;
        int r0 = m16 * 16 + gid, r1 = r0 + 8, c0 = ks2 * 16 + 2 * tig;
        const float* x0 = xs + r0 * 68;
        const float* x1 = xs + r1 * 68;
        uint4 w;
        w.x = h2u(x0[c0],     x0[c0 + 1]);
        w.y = h2u(x1[c0],     x1[c0 + 1]);
        w.z = h2u(x0[c0 + 8], x0[c0 + 9]);
        w.w = h2u(x1[c0 + 8], x1[c0 + 9]);
        *reinterpret_cast<uint4*>(dst + ent * 8) = w;
    }
}

// ---------------------------------------------------------------------------
// pack_w: w_pack[e][nt][kc] = 64(k)x128(n) tile of W^T, fp16, B-fragment layout.
// Entry (ks2 0..3, jp 0..7, lane) = {b0(j0),b1(j0),b0(j1),b1(j1)} packed half2s.
// ---------------------------------------------------------------------------
__global__ void pack_w_kernel(const float* __restrict__ W) {
    __shared__ float ws[64 * 132];
    const int blk = blockIdx.x;                  // (e*NT+nt)*16 + kc
    const int kc = blk & 15, nt = (blk >> 4) & 7, e = blk >> 7;
    const int tid = threadIdx.x;

    const float* src = W + ((size_t)e * D_IN + kc * BK) * D_OUT + nt * 128;
    for (int idx = tid; idx < 2048; idx += 256) {
        int il = idx >> 5, o4 = idx & 31;
        float4 v = *reinterpret_cast<const float4*>(src + (size_t)il * D_OUT + o4 * 4);
        *reinterpret_cast<float4*>(ws + il * 132 + o4 * 4) = v;
    }
    __syncthreads();

    __half* dst = w_pack + (size_t)blk * 8192;
#pragma unroll
    for (int q = 0; q < 4; q++) {
        int ent = tid + q * 256;                 // 0..1023
        int lane = ent & 31, jp = (ent >> 5) & 7, ks2 = ent >> 8;
        int gid = lane >> 2, tig = lane & 3;
        int kr = ks2 * 16 + 2 * tig;
        int cA = jp * 16 + gid, cB = cA + 8;
        uint4 w;
        w.x = h2u(ws[kr * 132 + cA],       ws[(kr + 1) * 132 + cA]);
        w.y = h2u(ws[(kr + 8) * 132 + cA], ws[(kr + 9) * 132 + cA]);
        w.z = h2u(ws[kr * 132 + cB],       ws[(kr + 1) * 132 + cB]);
        w.w = h2u(ws[(kr + 8) * 132 + cB], ws[(kr + 9) * 132 + cB]);
        *reinterpret_cast<uint4*>(dst + ent * 8) = w;
    }
}

// ---------------------------------------------------------------------------
// Hot GEMM: 128x128 CTA tile, 4 warps 2(m) x 2(n), warp tile 64x64, occ 2.
// BK=64 (4 ks2 per iter), 3-stage cp.async pipeline, one barrier per iter.
// A ungated in SMEM; gate applied to A fragments in registers (HMUL2).
// ---------------------------------------------------------------------------
__global__ void __launch_bounds__(NTHREADS, 2)
moe_mma_kernel(const float* __restrict__ bias, float* __restrict__ out) {
    extern __shared__ char smem[];
    const int tid = threadIdx.x, wid = tid >> 5, lane = tid & 31;
    const int gid = lane >> 2, tig = lane & 3;
    const int wm = wid >> 1, wn = wid & 1;
    const int nt = blockIdx.x & 7, mt = blockIdx.x >> 3;
    const int m0 = mt * BM, n0 = nt * BN;
    const uint32_t sb = smem_u32(smem);

    float* g_s = reinterpret_cast<float*>(smem + SMEM_G);
    float* b_s = reinterpret_cast<float*>(smem + SMEM_BS);
    for (int i = tid; i < BM * N_EXP; i += NTHREADS) g_s[i] = g_gate[m0 * N_EXP + i];
    for (int i = tid; i < N_EXP * BN; i += NTHREADS)
        b_s[i] = bias[(size_t)(i >> 7) * D_OUT + n0 + (i & 127)];

    float acc[4][8][4];
#pragma unroll
    for (int a = 0; a < 4; a++)
#pragma unroll
        for (int b = 0; b < 8; b++)
#pragma unroll
            for (int c = 0; c < 4; c++) acc[a][b][c] = 0.f;

    auto issue = [&](int it, int buf) {
        const int e = it >> 4, kc = it & 15;
        const char* asrc = (const char*)(x_pack + (size_t)(mt * KCH + kc) * 8192);
        const char* bsrc = (const char*)(w_pack + (size_t)((e * NT + nt) * KCH + kc) * 8192);
        uint32_t d = sb + buf * STAGE_BYTES + tid * 16;
#pragma unroll
        for (int r = 0; r < 8; r++) cp16(d + r * 2048, asrc + tid * 16 + r * 2048);
#pragma unroll
        for (int r = 0; r < 8; r++)
            cp16(d + A_TILE_BYTES + r * 2048, bsrc + tid * 16 + r * 2048);
        cp_commit();
    };

    issue(0, 0);
    issue(1, 1);

    // publish g_s/b_s to all threads before any cross-warp read (R5 race fix)
    __syncthreads();

    // per-thread gate half2s for this thread's 8 A-fragment rows, per expert
    uint32_t g2[4][2];

    for (int e = 0; e < N_EXP; e++) {
#pragma unroll
        for (int mtt = 0; mtt < 4; mtt++) {
            int r0 = wm * 64 + mtt * 16 + gid;
            float gv0 = g_s[r0 * N_EXP + e];
            float gv1 = g_s[(r0 + 8) * N_EXP + e];
            g2[mtt][0] = h2u(gv0, gv0);
            g2[mtt][1] = h2u(gv1, gv1);
        }
        for (int kc = 0; kc < KCH; kc++) {
            const int it = e * KCH + kc;
            cp_wait1();                 // stage `it` landed
            __syncthreads();            // publish; stage it-1 fully consumed
            if (it + 2 < ITERS) issue(it + 2, (it + 2) % NSTAGE);

            const char* ab = smem + (it % NSTAGE) * STAGE_BYTES;
            const char* bb = ab + A_TILE_BYTES;
#pragma unroll
            for (int ks2 = 0; ks2 < 4; ks2++) {
                uint4 af[4], bf[4];
#pragma unroll
                for (int mtt = 0; mtt < 4; mtt++) {
                    af[mtt] = *reinterpret_cast<const uint4*>(
                        ab + (size_t)((ks2 * 8 + wm * 4 + mtt) * 32 + lane) * 16);
                    af[mtt].x = hmul2u(af[mtt].x, g2[mtt][0]);
                    af[mtt].y = hmul2u(af[mtt].y, g2[mtt][1]);
                    af[mtt].z = hmul2u(af[mtt].z, g2[mtt][0]);
                    af[mtt].w = hmul2u(af[mtt].w, g2[mtt][1]);
                }
#pragma unroll
                for (int jpi = 0; jpi < 4; jpi++)
                    bf[jpi] = *reinterpret_cast<const uint4*>(
                        bb + (size_t)((ks2 * 8 + wn * 4 + jpi) * 32 + lane) * 16);
#pragma unroll
                for (int mtt = 0; mtt < 4; mtt++)
#pragma unroll
                    for (int ntt = 0; ntt < 8; ntt++) {
                        const uint32_t* a = reinterpret_cast<const uint32_t*>(&af[mtt]);
                        const uint32_t* bp =
                            reinterpret_cast<const uint32_t*>(&bf[ntt >> 1]) + (ntt & 1) * 2;
                        mma_f16(acc[mtt][ntt], a, bp, acc[mtt][ntt]);
                    }
            }
        }
    }

    // ---- epilogue: gated bias + store ----
#pragma unroll
    for (int mtt = 0; mtt < 4; mtt++) {
        const int rb = wm * 64 + mtt * 16 + gid;
#pragma unroll
        for (int half = 0; half < 2; half++) {
            const int r = rb + half * 8;
            const float* gr = g_s + r * N_EXP;
            float* orow = out + (size_t)(m0 + r) * D_OUT + n0;
#pragma unroll
            for (int ntt = 0; ntt < 8; ntt++) {
                const int c = wn * 64 + ntt * 8 + 2 * tig;
                float b0 = 0.f, b1 = 0.f;
#pragma unroll
                for (int e = 0; e < N_EXP; e++) {
                    float gv = gr[e];
                    b0 += gv * b_s[e * BN + c];
                    b1 += gv * b_s[e * BN + c + 1];
                }
                float2 v;
                v.x = acc[mtt][ntt][half * 2 + 0] + b0;
                v.y = acc[mtt][ntt][half * 2 + 1] + b1;
                *reinterpret_cast<float2*>(orow + c) = v;
            }
        }
    }
}

// ---------------------------------------------------------------------------
extern "C" void kernel_launch(void* const* d_in, const int* in_sizes, int n_in,
                              void* d_out, int out_size) {
    const float* x      = (const float*)d_in[0];
    const float* W      = (const float*)d_in[1];
    const float* b      = (const float*)d_in[2];
    const float* gate_W = (const float*)d_in[3];
    const float* gate_b = (const float*)d_in[4];
    float* out = (float*)d_out;

    gate_kernel<<<N_TOKENS / 8, 256>>>(x, gate_W, gate_b);
    pack_x_kernel<<<MT * KCH, 256>>>(x);           // 1024 blocks
    pack_w_kernel<<<N_EXP * NT * KCH, 256>>>(W);   // 1024 blocks

    cudaFuncSetAttribute(moe_mma_kernel,
                         cudaFuncAttributeMaxDynamicSharedMemorySize, SMEM_TOTAL);
    moe_mma_kernel<<<MT * NT, NTHREADS, SMEM_TOTAL>>>(b, out);   // 512 CTAs
}

// round 9
// speedup vs baseline: 3.8619x; 1.0905x over previous
#include <cuda_runtime.h>
#include <cuda_fp16.h>
#include <math.h>
#include <stdint.h>

#define N_TOKENS 8192
#define D_IN     1024
#define D_OUT    1024
#define N_EXP    8

#define BM 128
#define BN 128
#define BK 64                    // floats per k-chunk
#define KCH (D_IN / BK)          // 16 chunks per expert
#define MT  (N_TOKENS / BM)      // 64
#define NT  (D_OUT / BN)         // 8
#define NPAIR 4                  // expert pairs
#define BSTEPS (KCH * NPAIR)     // 64 B-steps total
#define NTHREADS 128

#define A_TILE_BYTES 16384       // 128 x 64 fp16, fragment-packed
#define B_TILE_BYTES 16384       // 64 x 128 fp16, fragment-packed (per expert)
#define B_STAGE_BYTES (2 * B_TILE_BYTES)               // 32768 (expert pair)
#define SMEM_A   0                                     // 2 x 16384 = 32768
#define SMEM_B   32768                                 // 2 x 32768 = 65536
#define SMEM_G   98304                                 // gate 128x8 f32 (4096)
#define SMEM_BS  102400                                // bias 8x128 f32 (4096)
#define SMEM_TOTAL 106496                              // x2 CTA = 212992 < 228K

// ---------------------------------------------------------------------------
// scratch (device globals: no allocation allowed)
// ---------------------------------------------------------------------------
__device__ float  g_gate[N_TOKENS * N_EXP];
__device__ __half x_pack[(size_t)MT * KCH * 8192];           // 16 MB (ungated)
__device__ __half w_pack[(size_t)N_EXP * NT * KCH * 8192];   // 16 MB

// ---------------------------------------------------------------------------
// helpers
// ---------------------------------------------------------------------------
__device__ __forceinline__ uint32_t smem_u32(const void* p) {
    uint32_t a;
    asm("{ .reg .u64 t; cvta.to.shared.u64 t, %1; cvt.u32.u64 %0, t; }" : "=r"(a) : "l"(p));
    return a;
}
__device__ __forceinline__ void cp16(uint32_t d, const void* s) {
    asm volatile("cp.async.cg.shared.global [%0], [%1], 16;" :: "r"(d), "l"(s));
}
__device__ __forceinline__ void cp_commit() {
    asm volatile("cp.async.commit_group;" ::: "memory");
}
__device__ __forceinline__ void cp_wait0() {
    asm volatile("cp.async.wait_group 0;" ::: "memory");
}
__device__ __forceinline__ void mma_f16(float* d, const uint32_t* a,
                                        const uint32_t* b, const float* c) {
    asm volatile(
        "mma.sync.aligned.m16n8k16.row.col.f32.f16.f16.f32 "
        "{%0,%1,%2,%3}, {%4,%5,%6,%7}, {%8,%9}, {%10,%11,%12,%13};\n"
        : "=f"(d[0]), "=f"(d[1]), "=f"(d[2]), "=f"(d[3])
        : "r"(a[0]), "r"(a[1]), "r"(a[2]), "r"(a[3]),
          "r"(b[0]), "r"(b[1]),
          "f"(c[0]), "f"(c[1]), "f"(c[2]), "f"(c[3]));
}
__device__ __forceinline__ uint32_t h2u(float lo, float hi) {
    __half2 h = __halves2half2(__float2half_rn(lo), __float2half_rn(hi));
    return *reinterpret_cast<uint32_t*>(&h);
}
__device__ __forceinline__ uint32_t hmul2u(uint32_t a, uint32_t g) {
    __half2 r = __hmul2(*reinterpret_cast<__half2*>(&a), *reinterpret_cast<__half2*>(&g));
    return *reinterpret_cast<uint32_t*>(&r);
}

// ---------------------------------------------------------------------------
// Gate: g = softmax(x @ gate_W + gate_b), one warp per token
// ---------------------------------------------------------------------------
__global__ void gate_kernel(const float* __restrict__ x,
                            const float* __restrict__ gate_W,
                            const float* __restrict__ gate_b) {
    int warp = threadIdx.x >> 5, lane = threadIdx.x & 31;
    int token = blockIdx.x * 8 + warp;
    if (token >= N_TOKENS) return;
    const float* xr = x + (size_t)token * D_IN;
    float acc[N_EXP];
#pragma unroll
    for (int e = 0; e < N_EXP; e++) acc[e] = 0.f;
    for (int i = lane; i < D_IN; i += 32) {
        float xv = xr[i];
        const float4* gw = reinterpret_cast<const float4*>(gate_W + (size_t)i * N_EXP);
        float4 w0 = gw[0], w1 = gw[1];
        acc[0] += xv * w0.x; acc[1] += xv * w0.y; acc[2] += xv * w0.z; acc[3] += xv * w0.w;
        acc[4] += xv * w1.x; acc[5] += xv * w1.y; acc[6] += xv * w1.z; acc[7] += xv * w1.w;
    }
#pragma unroll
    for (int e = 0; e < N_EXP; e++)
#pragma unroll
        for (int o = 16; o > 0; o >>= 1)
            acc[e] += __shfl_xor_sync(0xffffffffu, acc[e], o);
    if (lane == 0) {
        float m = -1e30f;
#pragma unroll
        for (int e = 0; e < N_EXP; e++) { acc[e] += gate_b[e]; m = fmaxf(m, acc[e]); }
        float s = 0.f;
#pragma unroll
        for (int e = 0; e < N_EXP; e++) { acc[e] = expf(acc[e] - m); s += acc[e]; }
        float inv = 1.f / s;
#pragma unroll
        for (int e = 0; e < N_EXP; e++) g_gate[token * N_EXP + e] = acc[e] * inv;
    }
}

// ---------------------------------------------------------------------------
// pack_x: x_pack[mt][kc] = 128x64 tile of x, fp16, m16n8k16 A-fragment layout.
// ---------------------------------------------------------------------------
__global__ void pack_x_kernel(const float* __restrict__ x) {
    __shared__ float xs[128 * 68];
    const int blk = blockIdx.x;                  // mt*16 + kc
    const int kc = blk & 15, mt = blk >> 4;
    const int tid = threadIdx.x;

    const float* src = x + (size_t)(mt * BM) * D_IN + kc * BK;
    for (int idx = tid; idx < 2048; idx += 256) {
        int row = idx >> 4, c4 = idx & 15;
        float4 v = *reinterpret_cast<const float4*>(src + (size_t)row * D_IN + c4 * 4);
        *reinterpret_cast<float4*>(xs + row * 68 + c4 * 4) = v;
    }
    __syncthreads();

    __half* dst = x_pack + (size_t)blk * 8192;
#pragma unroll
    for (int q = 0; q < 4; q++) {
        int ent = tid + q * 256;                 // 0..1023
        int lane = ent & 31, m16 = (ent >> 5) & 7, ks2 = ent >> 8;
        int gid = lane >> 2, tig = lane & 3;
        int r0 = m16 * 16 + gid, r1 = r0 + 8, c0 = ks2 * 16 + 2 * tig;
        const float* x0 = xs + r0 * 68;
        const float* x1 = xs + r1 * 68;
        uint4 w;
        w.x = h2u(x0[c0],     x0[c0 + 1]);
        w.y = h2u(x1[c0],     x1[c0 + 1]);
        w.z = h2u(x0[c0 + 8], x0[c0 + 9]);
        w.w = h2u(x1[c0 + 8], x1[c0 + 9]);
        *reinterpret_cast<uint4*>(dst + ent * 8) = w;
    }
}

// ---------------------------------------------------------------------------
// pack_w: w_pack[e][nt][kc] = 64(k)x128(n) tile of W^T, fp16, B-fragment layout.
// ---------------------------------------------------------------------------
__global__ void pack_w_kernel(const float* __restrict__ W) {
    __shared__ float ws[64 * 132];
    const int blk = blockIdx.x;                  // (e*NT+nt)*16 + kc
    const int kc = blk & 15, nt = (blk >> 4) & 7, e = blk >> 7;
    const int tid = threadIdx.x;

    const float* src = W + ((size_t)e * D_IN + kc * BK) * D_OUT + nt * 128;
    for (int idx = tid; idx < 2048; idx += 256) {
        int il = idx >> 5, o4 = idx & 31;
        float4 v = *reinterpret_cast<const float4*>(src + (size_t)il * D_OUT + o4 * 4);
        *reinterpret_cast<float4*>(ws + il * 132 + o4 * 4) = v;
    }
    __syncthreads();

    __half* dst = w_pack + (size_t)blk * 8192;
#pragma unroll
    for (int q = 0; q < 4; q++) {
        int ent = tid + q * 256;                 // 0..1023
        int lane = ent & 31, jp = (ent >> 5) & 7, ks2 = ent >> 8;
        int gid = lane >> 2, tig = lane & 3;
        int kr = ks2 * 16 + 2 * tig;
        int cA = jp * 16 + gid, cB = cA + 8;
        uint4 w;
        w.x = h2u(ws[kr * 132 + cA],       ws[(kr + 1) * 132 + cA]);
        w.y = h2u(ws[(kr + 8) * 132 + cA], ws[(kr + 9) * 132 + cA]);
        w.z = h2u(ws[kr * 132 + cB],       ws[(kr + 1) * 132 + cB]);
        w.w = h2u(ws[(kr + 8) * 132 + cB], ws[(kr + 9) * 132 + cB]);
        *reinterpret_cast<uint4*>(dst + ent * 8) = w;
    }
}

// ---------------------------------------------------------------------------
// Hot GEMM: 128x128 CTA tile, 4 warps 2(m) x 2(n), warp tile 64x64, occ 2.
// Loop: kc { A staged once } x expert-pair { 2 B tiles } — A writes /8, A reads /2.
// Gate applied to A fragments in registers per expert (HMUL2).
// ---------------------------------------------------------------------------
__global__ void __launch_bounds__(NTHREADS, 2)
moe_mma_kernel(const float* __restrict__ bias, float* __restrict__ out) {
    extern __shared__ char smem[];
    const int tid = threadIdx.x, wid = tid >> 5, lane = tid & 31;
    const int gid = lane >> 2, tig = lane & 3;
    const int wm = wid >> 1, wn = wid & 1;
    const int nt = blockIdx.x & 7, mt = blockIdx.x >> 3;
    const int m0 = mt * BM, n0 = nt * BN;
    const uint32_t sb = smem_u32(smem);

    float* g_s = reinterpret_cast<float*>(smem + SMEM_G);
    float* b_s = reinterpret_cast<float*>(smem + SMEM_BS);
    for (int i = tid; i < BM * N_EXP; i += NTHREADS) g_s[i] = g_gate[m0 * N_EXP + i];
    for (int i = tid; i < N_EXP * BN; i += NTHREADS)
        b_s[i] = bias[(size_t)(i >> 7) * D_OUT + n0 + (i & 127)];

    float acc[4][8][4];
#pragma unroll
    for (int a = 0; a < 4; a++)
#pragma unroll
        for (int b = 0; b < 8; b++)
#pragma unroll
            for (int c = 0; c < 4; c++) acc[a][b][c] = 0.f;

    // stage issue helpers (8 cp16 per 16KB tile per thread)
    auto issueA = [&](int kc, int buf) {
        const char* src = (const char*)(x_pack + (size_t)(mt * KCH + kc) * 8192);
        uint32_t d = sb + SMEM_A + buf * A_TILE_BYTES + tid * 16;
#pragma unroll
        for (int r = 0; r < 8; r++) cp16(d + r * 2048, src + tid * 16 + r * 2048);
    };
    auto issueB = [&](int it, int buf) {
        const int kc = it >> 2, e0 = (it & 3) * 2;
        uint32_t d = sb + SMEM_B + buf * B_STAGE_BYTES + tid * 16;
#pragma unroll
        for (int ee = 0; ee < 2; ee++) {
            const char* src = (const char*)(
                w_pack + (size_t)(((e0 + ee) * NT + nt) * KCH + kc) * 8192);
#pragma unroll
            for (int r = 0; r < 8; r++)
                cp16(d + ee * B_TILE_BYTES + r * 2048, src + tid * 16 + r * 2048);
        }
    };

    // prologue: A0 + B0 in one group
    issueA(0, 0);
    issueB(0, 0);
    cp_commit();

    for (int it = 0; it < BSTEPS; ++it) {
        const int kc = it >> 2, e0 = (it & 3) * 2;
        cp_wait0();                  // stage `it` (and pending A) landed for this thread
        __syncthreads();             // publish; all warps done with step it-1

        // issue next B (and next A at kc boundary) — overlaps compute of `it`
        if (it + 1 < BSTEPS) {
            issueB(it + 1, (it + 1) & 1);
            if ((it & 3) == 0 && kc + 1 < KCH) issueA(kc + 1, (kc + 1) & 1);
            cp_commit();
        }

        // per-expert gate half2s for this thread's 8 A-fragment rows
        uint32_t g2e[2][4][2];
#pragma unroll
        for (int ee = 0; ee < 2; ee++)
#pragma unroll
            for (int mtt = 0; mtt < 4; mtt++) {
                int r0 = wm * 64 + mtt * 16 + gid;
                float gv0 = g_s[r0 * N_EXP + e0 + ee];
                float gv1 = g_s[(r0 + 8) * N_EXP + e0 + ee];
                g2e[ee][mtt][0] = h2u(gv0, gv0);
                g2e[ee][mtt][1] = h2u(gv1, gv1);
            }

        const char* ab = smem + SMEM_A + (kc & 1) * A_TILE_BYTES;
        const char* bb = smem + SMEM_B + (it & 1) * B_STAGE_BYTES;
#pragma unroll
        for (int ks2 = 0; ks2 < 4; ks2++) {
            uint4 af[4];
#pragma unroll
            for (int mtt = 0; mtt < 4; mtt++)
                af[mtt] = *reinterpret_cast<const uint4*>(
                    ab + (size_t)((ks2 * 8 + wm * 4 + mtt) * 32 + lane) * 16);
#pragma unroll
            for (int ee = 0; ee < 2; ee++) {
                uint4 bf[4];
#pragma unroll
                for (int jpi = 0; jpi < 4; jpi++)
                    bf[jpi] = *reinterpret_cast<const uint4*>(
                        bb + ee * B_TILE_BYTES +
                        (size_t)((ks2 * 8 + wn * 4 + jpi) * 32 + lane) * 16);
                uint4 afg[4];
#pragma unroll
                for (int mtt = 0; mtt < 4; mtt++) {
                    afg[mtt].x = hmul2u(af[mtt].x, g2e[ee][mtt][0]);
                    afg[mtt].y = hmul2u(af[mtt].y, g2e[ee][mtt][1]);
                    afg[mtt].z = hmul2u(af[mtt].z, g2e[ee][mtt][0]);
                    afg[mtt].w = hmul2u(af[mtt].w, g2e[ee][mtt][1]);
                }
#pragma unroll
                for (int mtt = 0; mtt < 4; mtt++)
#pragma unroll
                    for (int ntt = 0; ntt < 8; ntt++) {
                        const uint32_t* a = reinterpret_cast<const uint32_t*>(&afg[mtt]);
                        const uint32_t* bp =
                            reinterpret_cast<const uint32_t*>(&bf[ntt >> 1]) + (ntt & 1) * 2;
                        mma_f16(acc[mtt][ntt], a, bp, acc[mtt][ntt]);
                    }
            }
        }
    }

    // ---- epilogue: gated bias + store ----
#pragma unroll
    for (int mtt = 0; mtt < 4; mtt++) {
        const int rb = wm * 64 + mtt * 16 + gid;
#pragma unroll
        for (int half = 0; half < 2; half++) {
            const int r = rb + half * 8;
            const float* gr = g_s + r * N_EXP;
            float* orow = out + (size_t)(m0 + r) * D_OUT + n0;
#pragma unroll
            for (int ntt = 0; ntt < 8; ntt++) {
                const int c = wn * 64 + ntt * 8 + 2 * tig;
                float b0 = 0.f, b1 = 0.f;
#pragma unroll
                for (int e = 0; e < N_EXP; e++) {
                    float gv = gr[e];
                    b0 += gv * b_s[e * BN + c];
                    b1 += gv * b_s[e * BN + c + 1];
                }
                float2 v;
                v.x = acc[mtt][ntt][half * 2 + 0] + b0;
                v.y = acc[mtt][ntt][half * 2 + 1] + b1;
                *reinterpret_cast<float2*>(orow + c) = v;
            }
        }
    }
}

// ---------------------------------------------------------------------------
extern "C" void kernel_launch(void* const* d_in, const int* in_sizes, int n_in,
                              void* d_out, int out_size) {
    const float* x      = (const float*)d_in[0];
    const float* W      = (const float*)d_in[1];
    const float* b      = (const float*)d_in[2];
    const float* gate_W = (const float*)d_in[3];
    const float* gate_b = (const float*)d_in[4];
    float* out = (float*)d_out;

    gate_kernel<<<N_TOKENS / 8, 256>>>(x, gate_W, gate_b);
    pack_x_kernel<<<MT * KCH, 256>>>(x);           // 1024 blocks
    pack_w_kernel<<<N_EXP * NT * KCH, 256>>>(W);   // 1024 blocks

    cudaFuncSetAttribute(moe_mma_kernel,
                         cudaFuncAttributeMaxDynamicSharedMemorySize, SMEM_TOTAL);
    moe_mma_kernel<<<MT * NT, NTHREADS, SMEM_TOTAL>>>(b, out);   // 512 CTAs
}

// round 10
// speedup vs baseline: 3.8687x; 1.0018x over previous
#include <cuda_runtime.h>
#include <cuda_fp16.h>
#include <math.h>
#include <stdint.h>

#define N_TOKENS 8192
#define D_IN     1024
#define D_OUT    1024
#define N_EXP    8

#define BM 128
#define BN 128
#define BK 64                    // floats per k-chunk
#define KCH (D_IN / BK)          // 16 chunks per expert
#define MT  (N_TOKENS / BM)      // 64
#define NT  (D_OUT / BN)         // 8
#define NPAIR 4                  // expert pairs
#define BSTEPS (KCH * NPAIR)     // 64 B-steps total
#define NTHREADS 128

#define A_TILE_BYTES 16384       // 128 x 64 fp16, fragment-packed
#define B_TILE_BYTES 16384       // 64 x 128 fp16, fragment-packed (per expert)
#define B_STAGE_BYTES (2 * B_TILE_BYTES)               // 32768 (expert pair)
#define SMEM_A   0                                     // 2 x 16384 = 32768
#define SMEM_B   32768                                 // 2 x 32768 = 65536
#define SMEM_G   98304                                 // gate 128x8 f32 (4096)
#define SMEM_BS  102400                                // bias 8x128 f32 (4096)
#define SMEM_TOTAL 106496                              // x2 CTA = 212992 < 228K

// ---------------------------------------------------------------------------
// scratch (device globals: no allocation allowed)
// ---------------------------------------------------------------------------
__device__ float  g_gate[N_TOKENS * N_EXP];
__device__ __half x_pack[(size_t)MT * KCH * 8192];           // 16 MB (ungated)
__device__ __half w_pack[(size_t)N_EXP * NT * KCH * 8192];   // 16 MB

// ---------------------------------------------------------------------------
// helpers
// ---------------------------------------------------------------------------
__device__ __forceinline__ uint32_t smem_u32(const void* p) {
    uint32_t a;
    asm("{ .reg .u64 t; cvta.to.shared.u64 t, %1; cvt.u32.u64 %0, t; }" : "=r"(a) : "l"(p));
    return a;
}
__device__ __forceinline__ void cp16(uint32_t d, const void* s) {
    asm volatile("cp.async.cg.shared.global [%0], [%1], 16;" :: "r"(d), "l"(s));
}
__device__ __forceinline__ void cp_commit() {
    asm volatile("cp.async.commit_group;" ::: "memory");
}
__device__ __forceinline__ void cp_wait0() {
    asm volatile("cp.async.wait_group 0;" ::: "memory");
}
__device__ __forceinline__ void mma_f16(float* d, const uint32_t* a,
                                        const uint32_t* b, const float* c) {
    asm volatile(
        "mma.sync.aligned.m16n8k16.row.col.f32.f16.f16.f32 "
        "{%0,%1,%2,%3}, {%4,%5,%6,%7}, {%8,%9}, {%10,%11,%12,%13};\n"
        : "=f"(d[0]), "=f"(d[1]), "=f"(d[2]), "=f"(d[3])
        : "r"(a[0]), "r"(a[1]), "r"(a[2]), "r"(a[3]),
          "r"(b[0]), "r"(b[1]),
          "f"(c[0]), "f"(c[1]), "f"(c[2]), "f"(c[3]));
}
__device__ __forceinline__ uint32_t h2u(float lo, float hi) {
    __half2 h = __halves2half2(__float2half_rn(lo), __float2half_rn(hi));
    return *reinterpret_cast<uint32_t*>(&h);
}
__device__ __forceinline__ uint32_t hmul2u(uint32_t a, uint32_t g) {
    __half2 r = __hmul2(*reinterpret_cast<__half2*>(&a), *reinterpret_cast<__half2*>(&g));
    return *reinterpret_cast<uint32_t*>(&r);
}

// ---------------------------------------------------------------------------
// Gate: g = softmax(x @ gate_W + gate_b), one warp per token
// ---------------------------------------------------------------------------
__global__ void gate_kernel(const float* __restrict__ x,
                            const float* __restrict__ gate_W,
                            const float* __restrict__ gate_b) {
    int warp = threadIdx.x >> 5, lane = threadIdx.x & 31;
    int token = blockIdx.x * 8 + warp;
    if (token >= N_TOKENS) return;
    const float* xr = x + (size_t)token * D_IN;
    float acc[N_EXP];
#pragma unroll
    for (int e = 0; e < N_EXP; e++) acc[e] = 0.f;
    for (int i = lane; i < D_IN; i += 32) {
        float xv = xr[i];
        const float4* gw = reinterpret_cast<const float4*>(gate_W + (size_t)i * N_EXP);
        float4 w0 = gw[0], w1 = gw[1];
        acc[0] += xv * w0.x; acc[1] += xv * w0.y; acc[2] += xv * w0.z; acc[3] += xv * w0.w;
        acc[4] += xv * w1.x; acc[5] += xv * w1.y; acc[6] += xv * w1.z; acc[7] += xv * w1.w;
    }
#pragma unroll
    for (int e = 0; e < N_EXP; e++)
#pragma unroll
        for (int o = 16; o > 0; o >>= 1)
            acc[e] += __shfl_xor_sync(0xffffffffu, acc[e], o);
    if (lane == 0) {
        float m = -1e30f;
#pragma unroll
        for (int e = 0; e < N_EXP; e++) { acc[e] += gate_b[e]; m = fmaxf(m, acc[e]); }
        float s = 0.f;
#pragma unroll
        for (int e = 0; e < N_EXP; e++) { acc[e] = expf(acc[e] - m); s += acc[e]; }
        float inv = 1.f / s;
#pragma unroll
        for (int e = 0; e < N_EXP; e++) g_gate[token * N_EXP + e] = acc[e] * inv;
    }
}

// ---------------------------------------------------------------------------
// pack_x: x_pack[mt][kc] = 128x64 tile of x, fp16, m16n8k16 A-fragment layout.
// ---------------------------------------------------------------------------
__global__ void pack_x_kernel(const float* __restrict__ x) {
    __shared__ float xs[128 * 68];
    const int blk = blockIdx.x;                  // mt*16 + kc
    const int kc = blk & 15, mt = blk >> 4;
    const int tid = threadIdx.x;

    const float* src = x + (size_t)(mt * BM) * D_IN + kc * BK;
    for (int idx = tid; idx < 2048; idx += 256) {
        int row = idx >> 4, c4 = idx & 15;
        float4 v = *reinterpret_cast<const float4*>(src + (size_t)row * D_IN + c4 * 4);
        *reinterpret_cast<float4*>(xs + row * 68 + c4 * 4) = v;
    }
    __syncthreads();

    __half* dst = x_pack + (size_t)blk * 8192;
#pragma unroll
    for (int q = 0; q < 4; q++) {
        int ent = tid + q * 256;                 // 0..1023
        int lane = ent & 31, m16 = (ent >> 5) & 7, ks2 = ent >> 8;
        int gid = lane >> 2, tig = lane & 3;
        int r0 = m16 * 16 + gid, r1 = r0 + 8, c0 = ks2 * 16 + 2 * tig;
        const float* x0 = xs + r0 * 68;
        const float* x1 = xs + r1 * 68;
        uint4 w;
        w.x = h2u(x0[c0],     x0[c0 + 1]);
        w.y = h2u(x1[c0],     x1[c0 + 1]);
        w.z = h2u(x0[c0 + 8], x0[c0 + 9]);
        w.w = h2u(x1[c0 + 8], x1[c0 + 9]);
        *reinterpret_cast<uint4*>(dst + ent * 8) = w;
    }
}

// ---------------------------------------------------------------------------
// pack_w: w_pack[e][nt][kc] = 64(k)x128(n) tile of W^T, fp16, B-fragment layout.
// ---------------------------------------------------------------------------
__global__ void pack_w_kernel(const float* __restrict__ W) {
    __shared__ float ws[64 * 132];
    const int blk = blockIdx.x;                  // (e*NT+nt)*16 + kc
    const int kc = blk & 15, nt = (blk >> 4) & 7, e = blk >> 7;
    const int tid = threadIdx.x;

    const float* src = W + ((size_t)e * D_IN + kc * BK) * D_OUT + nt * 128;
    for (int idx = tid; idx < 2048; idx += 256) {
        int il = idx >> 5, o4 = idx & 31;
        float4 v = *reinterpret_cast<const float4*>(src + (size_t)il * D_OUT + o4 * 4);
        *reinterpret_cast<float4*>(ws + il * 132 + o4 * 4) = v;
    }
    __syncthreads();

    __half* dst = w_pack + (size_t)blk * 8192;
#pragma unroll
    for (int q = 0; q < 4; q++) {
        int ent = tid + q * 256;                 // 0..1023
        int lane = ent & 31, jp = (ent >> 5) & 7, ks2 = ent >> 8;
        int gid = lane >> 2, tig = lane & 3;
        int kr = ks2 * 16 + 2 * tig;
        int cA = jp * 16 + gid, cB = cA + 8;
        uint4 w;
        w.x = h2u(ws[kr * 132 + cA],       ws[(kr + 1) * 132 + cA]);
        w.y = h2u(ws[(kr + 8) * 132 + cA], ws[(kr + 9) * 132 + cA]);
        w.z = h2u(ws[kr * 132 + cB],       ws[(kr + 1) * 132 + cB]);
        w.w = h2u(ws[(kr + 8) * 132 + cB], ws[(kr + 9) * 132 + cB]);
        *reinterpret_cast<uint4*>(dst + ent * 8) = w;
    }
}

// ---------------------------------------------------------------------------
// Hot GEMM: 128x128 CTA tile, 4 warps 2(m) x 2(n), warp tile 64x64, occ 2.
// Loop: kc { A staged once } x expert-pair { 2 B tiles } — A writes /8, A reads /2.
// Gate applied to A fragments in registers per expert (HMUL2).
// ---------------------------------------------------------------------------
__global__ void __launch_bounds__(NTHREADS, 2)
moe_mma_kernel(const float* __restrict__ bias, float* __restrict__ out) {
    extern __shared__ char smem[];
    const int tid = threadIdx.x, wid = tid >> 5, lane = tid & 31;
    const int gid = lane >> 2, tig = lane & 3;
    const int wm = wid >> 1, wn = wid & 1;
    const int nt = blockIdx.x & 7, mt = blockIdx.x >> 3;
    const int m0 = mt * BM, n0 = nt * BN;
    const uint32_t sb = smem_u32(smem);

    float* g_s = reinterpret_cast<float*>(smem + SMEM_G);
    float* b_s = reinterpret_cast<float*>(smem + SMEM_BS);
    for (int i = tid; i < BM * N_EXP; i += NTHREADS) g_s[i] = g_gate[m0 * N_EXP + i];
    for (int i = tid; i < N_EXP * BN; i += NTHREADS)
        b_s[i] = bias[(size_t)(i >> 7) * D_OUT + n0 + (i & 127)];

    float acc[4][8][4];
#pragma unroll
    for (int a = 0; a < 4; a++)
#pragma unroll
        for (int b = 0; b < 8; b++)
#pragma unroll
            for (int c = 0; c < 4; c++) acc[a][b][c] = 0.f;

    // stage issue helpers (8 cp16 per 16KB tile per thread)
    auto issueA = [&](int kc, int buf) {
        const char* src = (const char*)(x_pack + (size_t)(mt * KCH + kc) * 8192);
        uint32_t d = sb + SMEM_A + buf * A_TILE_BYTES + tid * 16;
#pragma unroll
        for (int r = 0; r < 8; r++) cp16(d + r * 2048, src + tid * 16 + r * 2048);
    };
    auto issueB = [&](int it, int buf) {
        const int kc = it >> 2, e0 = (it & 3) * 2;
        uint32_t d = sb + SMEM_B + buf * B_STAGE_BYTES + tid * 16;
#pragma unroll
        for (int ee = 0; ee < 2; ee++) {
            const char* src = (const char*)(
                w_pack + (size_t)(((e0 + ee) * NT + nt) * KCH + kc) * 8192);
#pragma unroll
            for (int r = 0; r < 8; r++)
                cp16(d + ee * B_TILE_BYTES + r * 2048, src + tid * 16 + r * 2048);
        }
    };

    // prologue: A0 + B0 in one group
    issueA(0, 0);
    issueB(0, 0);
    cp_commit();

    for (int it = 0; it < BSTEPS; ++it) {
        const int kc = it >> 2, e0 = (it & 3) * 2;
        cp_wait0();                  // stage `it` (and pending A) landed for this thread
        __syncthreads();             // publish; all warps done with step it-1

        // issue next B (and next A at kc boundary) — overlaps compute of `it`
        if (it + 1 < BSTEPS) {
            issueB(it + 1, (it + 1) & 1);
            if ((it & 3) == 0 && kc + 1 < KCH) issueA(kc + 1, (kc + 1) & 1);
            cp_commit();
        }

        // per-expert gate half2s for this thread's 8 A-fragment rows
        uint32_t g2e[2][4][2];
#pragma unroll
        for (int ee = 0; ee < 2; ee++)
#pragma unroll
            for (int mtt = 0; mtt < 4; mtt++) {
                int r0 = wm * 64 + mtt * 16 + gid;
                float gv0 = g_s[r0 * N_EXP + e0 + ee];
                float gv1 = g_s[(r0 + 8) * N_EXP + e0 + ee];
                g2e[ee][mtt][0] = h2u(gv0, gv0);
                g2e[ee][mtt][1] = h2u(gv1, gv1);
            }

        const char* ab = smem + SMEM_A + (kc & 1) * A_TILE_BYTES;
        const char* bb = smem + SMEM_B + (it & 1) * B_STAGE_BYTES;
#pragma unroll
        for (int ks2 = 0; ks2 < 4; ks2++) {
            uint4 af[4];
#pragma unroll
            for (int mtt = 0; mtt < 4; mtt++)
                af[mtt] = *reinterpret_cast<const uint4*>(
                    ab + (size_t)((ks2 * 8 + wm * 4 + mtt) * 32 + lane) * 16);
#pragma unroll
            for (int ee = 0; ee < 2; ee++) {
                uint4 bf[4];
#pragma unroll
                for (int jpi = 0; jpi < 4; jpi++)
                    bf[jpi] = *reinterpret_cast<const uint4*>(
                        bb + ee * B_TILE_BYTES +
                        (size_t)((ks2 * 8 + wn * 4 + jpi) * 32 + lane) * 16);
                uint4 afg[4];
#pragma unroll
                for (int mtt = 0; mtt < 4; mtt++) {
                    afg[mtt].x = hmul2u(af[mtt].x, g2e[ee][mtt][0]);
                    afg[mtt].y = hmul2u(af[mtt].y, g2e[ee][mtt][1]);
                    afg[mtt].z = hmul2u(af[mtt].z, g2e[ee][mtt][0]);
                    afg[mtt].w = hmul2u(af[mtt].w, g2e[ee][mtt][1]);
                }
#pragma unroll
                for (int mtt = 0; mtt < 4; mtt++)
#pragma unroll
                    for (int ntt = 0; ntt < 8; ntt++) {
                        const uint32_t* a = reinterpret_cast<const uint32_t*>(&afg[mtt]);
                        const uint32_t* bp =
                            reinterpret_cast<const uint32_t*>(&bf[ntt >> 1]) + (ntt & 1) * 2;
                        mma_f16(acc[mtt][ntt], a, bp, acc[mtt][ntt]);
                    }
            }
        }
    }

    // ---- epilogue: gated bias + store ----
#pragma unroll
    for (int mtt = 0; mtt < 4; mtt++) {
        const int rb = wm * 64 + mtt * 16 + gid;
#pragma unroll
        for (int half = 0; half < 2; half++) {
            const int r = rb + half * 8;
            const float* gr = g_s + r * N_EXP;
            float* orow = out + (size_t)(m0 + r) * D_OUT + n0;
#pragma unroll
            for (int ntt = 0; ntt < 8; ntt++) {
                const int c = wn * 64 + ntt * 8 + 2 * tig;
                float b0 = 0.f, b1 = 0.f;
#pragma unroll
                for (int e = 0; e < N_EXP; e++) {
                    float gv = gr[e];
                    b0 += gv * b_s[e * BN + c];
                    b1 += gv * b_s[e * BN + c + 1];
                }
                float2 v;
                v.x = acc[mtt][ntt][half * 2 + 0] + b0;
                v.y = acc[mtt][ntt][half * 2 + 1] + b1;
                *reinterpret_cast<float2*>(orow + c) = v;
            }
        }
    }
}

// ---------------------------------------------------------------------------
extern "C" void kernel_launch(void* const* d_in, const int* in_sizes, int n_in,
                              void* d_out, int out_size) {
    const float* x      = (const float*)d_in[0];
    const float* W      = (const float*)d_in[1];
    const float* b      = (const float*)d_in[2];
    const float* gate_W = (const float*)d_in[3];
    const float* gate_b = (const float*)d_in[4];
    float* out = (float*)d_out;

    gate_kernel<<<N_TOKENS / 8, 256>>>(x, gate_W, gate_b);
    pack_x_kernel<<<MT * KCH, 256>>>(x);           // 1024 blocks
    pack_w_kernel<<<N_EXP * NT * KCH, 256>>>(W);   // 1024 blocks

    cudaFuncSetAttribute(moe_mma_kernel,
                         cudaFuncAttributeMaxDynamicSharedMemorySize, SMEM_TOTAL);
    moe_mma_kernel<<<MT * NT, NTHREADS, SMEM_TOTAL>>>(b, out);   // 512 CTAs
}